// round 11
// baseline (speedup 1.0000x reference)
#include <cuda_runtime.h>
#include <cuda_bf16.h>
#include <cuda_fp16.h>
#include <cooperative_groups.h>
#include <cstdint>

namespace cg = cooperative_groups;

// ---------------- problem constants ----------------
#define VOCAB   50257
#define VOCAB_PAD 50432           // 394 * 128
#define DEMB    512
#define RES     2048
#define ROUT    512
#define BATCH   8
#define TLEN    256
#define BT      (BATCH*TLEN)      // 2048
#define KCA     512               // stored A: [Ah]           (fp16)
#define KCB     1024              // stored B: [Bh | Bl]      (fp16)
#define WR_SLOTS 64
#define WI_SLOTS 32
#define FULLW   0xffffffffu

// ---------------- device scratch (no allocs allowed) ----------------
__device__ float g_emb_proj[BT * RES];
__device__ float g_hs      [BT * RES];
__device__ float g_wr_val  [RES * WR_SLOTS];
__device__ int   g_wr_idx  [RES * WR_SLOTS];
__device__ int   g_wr_cnt  [RES];
__device__ float g_ws_val  [RES * WR_SLOTS];   // bank-scheduled
__device__ int   g_ws_idx  [RES * WR_SLOTS];
__device__ int   g_ws_cnt  [RES];              // warp-uniform slot bound
__device__ float g_wi_val  [RES * WI_SLOTS];
__device__ int   g_wi_idx  [RES * WI_SLOTS];
__device__ __half g_acat[BT * KCA];            // 2.1 MB
__device__ __half g_bcat[VOCAB_PAD * KCB];     // 103 MB

// ---------------- small PTX helpers (sm_80-compatible only) ----------------
__device__ __forceinline__ uint32_t smem_u32(const void* p) {
    uint32_t a;
    asm("{ .reg .u64 t; cvta.to.shared.u64 t, %1; cvt.u32.u64 %0, t; }" : "=r"(a) : "l"(p));
    return a;
}
__device__ __forceinline__ void cp16(uint32_t saddr, const void* g) {
    asm volatile("cp.async.cg.shared.global [%0], [%1], 16;" :: "r"(saddr), "l"(g) : "memory");
}
__device__ __forceinline__ void cp_commit() { asm volatile("cp.async.commit_group;" ::: "memory"); }
template<int N> __device__ __forceinline__ void cp_wait() {
    asm volatile("cp.async.wait_group %0;" :: "n"(N) : "memory");
}
__device__ __forceinline__ void ldsm4(uint32_t r[4], uint32_t addr) {
    asm volatile("ldmatrix.sync.aligned.m8n8.x4.shared.b16 {%0,%1,%2,%3}, [%4];"
                 : "=r"(r[0]), "=r"(r[1]), "=r"(r[2]), "=r"(r[3]) : "r"(addr));
}
__device__ __forceinline__ void mma16816(float c[4], const uint32_t a[4],
                                         uint32_t b0, uint32_t b1) {
    asm volatile("mma.sync.aligned.m16n8k16.row.col.f32.f16.f16.f32 "
                 "{%0,%1,%2,%3}, {%4,%5,%6,%7}, {%8,%9}, {%0,%1,%2,%3};"
                 : "+f"(c[0]), "+f"(c[1]), "+f"(c[2]), "+f"(c[3])
                 : "r"(a[0]), "r"(a[1]), "r"(a[2]), "r"(a[3]), "r"(b0), "r"(b1));
}

// ---------------- f32x2 packed-FMA helpers (proj GEMM) ----------------
__device__ __forceinline__ unsigned long long pk2(float x, float y) {
    unsigned long long r;
    asm("mov.b64 %0, {%1, %2};" : "=l"(r) : "f"(x), "f"(y));
    return r;
}
__device__ __forceinline__ void fma2(unsigned long long& d, unsigned long long a, unsigned long long b) {
    asm("fma.rn.f32x2 %0, %1, %2, %0;" : "+l"(d) : "l"(a), "l"(b));
}
__device__ __forceinline__ float2 upk2(unsigned long long v) {
    float2 r;
    asm("mov.b64 {%0, %1}, %2;" : "=f"(r.x), "=f"(r.y) : "l"(v));
    return r;
}

// ---------------- 1) sparsify W_rec ----------------
__global__ void sparsify_wrec_kernel(const float* __restrict__ W) {
    int warp = blockIdx.x * (blockDim.x >> 5) + (threadIdx.x >> 5);
    int lane = threadIdx.x & 31;
    if (warp >= RES) return;
    const float* row = W + (size_t)warp * RES;
    int base = 0;
    for (int j0 = 0; j0 < RES; j0 += 32) {
        float v = row[j0 + lane];
        unsigned m = __ballot_sync(FULLW, v != 0.0f);
        int pref = __popc(m & ((1u << lane) - 1u));
        if (v != 0.0f) {
            int pos = base + pref;
            if (pos < WR_SLOTS) {
                g_wr_val[warp * WR_SLOTS + pos] = v;
                g_wr_idx[warp * WR_SLOTS + pos] = j0 + lane;
            }
        }
        base += __popc(m);
    }
    int bb = base < WR_SLOTS ? base : WR_SLOTS;
    if (lane == 0) g_wr_cnt[warp] = bb;
    for (int s = bb + lane; s < WR_SLOTS; s += 32) {
        g_wr_val[warp * WR_SLOTS + s] = 0.0f;
        g_wr_idx[warp * WR_SLOTS + s] = 0;
    }
}

// ---------------- 1b) bank-schedule W_rec slots per recurrence warp ----------------
// One warp handles 32 consecutive rows (= one recurrence warp). Greedy per-slot
// assignment so the 32 lanes hit distinct smem banks (bank = idx % 32).
__global__ __launch_bounds__(256) void schedule_wrec_kernel() {
    int g    = (blockIdx.x * blockDim.x + threadIdx.x) >> 5;   // group 0..63
    int lane = threadIdx.x & 31;
    if (g >= RES / 32) return;
    const int row = g * 32 + lane;
    const int cnt = g_wr_cnt[row];

    // counting sort of this row's nnz by bank
    float sv[WR_SLOTS]; int si[WR_SLOTS];
    int bcnt[32];
#pragma unroll
    for (int b = 0; b < 32; b++) bcnt[b] = 0;
    for (int s = 0; s < cnt; s++) bcnt[g_wr_idx[row * WR_SLOTS + s] & 31]++;
    int bstart[32], bend[32];
    {
        int run = 0;
        for (int b = 0; b < 32; b++) { bstart[b] = run; run += bcnt[b]; bend[b] = run; }
    }
    int bfill[32];
#pragma unroll
    for (int b = 0; b < 32; b++) bfill[b] = bstart[b];
    for (int s = 0; s < cnt; s++) {
        int idx = g_wr_idx[row * WR_SLOTS + s];
        float v  = g_wr_val[row * WR_SLOTS + s];
        int b = idx & 31;
        sv[bfill[b]] = v; si[bfill[b]] = idx; bfill[b]++;
    }
    int bpos[32];
#pragma unroll
    for (int b = 0; b < 32; b++) bpos[b] = bstart[b];
    unsigned bank_mask = 0;
#pragma unroll
    for (int b = 0; b < 32; b++) if (bcnt[b]) bank_mask |= 1u << b;
    int rem = cnt;

    for (int s = 0; s < WR_SLOTS; s++) {
        unsigned used = 0;
        bool committed = (rem == 0);
        float cv = 0.0f;
        int   ci = lane;                 // pad: unique bank per lane
        while (__ballot_sync(FULLW, !committed)) {
            int b = 0xFF; bool force = false;
            if (!committed) {
                unsigned avail = bank_mask & ~used;
                unsigned pool  = avail ? avail : bank_mask;
                force = (avail == 0);
                // lane-rotated first-set-bit to spread proposals
                unsigned rot = (pool >> lane) | (pool << ((32 - lane) & 31));
                b = ((__ffs(rot) - 1) + lane) & 31;
            }
            unsigned grp = __match_any_sync(FULLW, b);
            bool win = !committed && (force || ((int)(__ffs(grp) - 1) == lane));
            unsigned ub = 0;
            if (win) {
                cv = sv[bpos[b]]; ci = si[bpos[b]];
                bpos[b]++;
                if (bpos[b] == bend[b]) bank_mask &= ~(1u << b);
                rem--; committed = true; ub = 1u << b;
            }
            used |= __reduce_or_sync(FULLW, ub);
        }
        g_ws_val[row * WR_SLOTS + s] = cv;
        g_ws_idx[row * WR_SLOTS + s] = ci;
    }
    // warp-uniform slot bound (items are never delayed past own cnt)
    int scnt = __reduce_max_sync(FULLW, cnt);
    g_ws_cnt[row] = (scnt + 3) & ~3;     // round up to 4 for the 4-way gather
}

// ---------------- 2) sparsify W_in ----------------
__global__ void sparsify_win_kernel(const float* __restrict__ W) {
    int col  = blockIdx.x * (blockDim.x >> 5) + (threadIdx.x >> 5);
    int lane = threadIdx.x & 31;
    if (col >= RES) return;
    int base = 0;
    for (int d0 = 0; d0 < DEMB; d0 += 32) {
        float v = W[(size_t)(d0 + lane) * RES + col];
        unsigned m = __ballot_sync(FULLW, v != 0.0f);
        int pref = __popc(m & ((1u << lane) - 1u));
        if (v != 0.0f) {
            int pos = base + pref;
            if (pos < WI_SLOTS) {
                g_wi_val[col * WI_SLOTS + pos] = v;
                g_wi_idx[col * WI_SLOTS + pos] = d0 + lane;
            }
        }
        base += __popc(m);
    }
    int bb = base < WI_SLOTS ? base : WI_SLOTS;
    for (int s = bb + lane; s < WI_SLOTS; s += 32) {
        g_wi_val[col * WI_SLOTS + s] = 0.0f;
        g_wi_idx[col * WI_SLOTS + s] = 0;
    }
}

// ---------------- 3) embed + sparse input projection ----------------
__global__ __launch_bounds__(256) void embed_proj_kernel(
    const int* __restrict__ xg, const float* __restrict__ tok_emb)
{
    __shared__ __align__(16) float emb_sm[DEMB][20];
    const int bt0 = blockIdx.x * 16;
    const int rbase = blockIdx.y * 1024;
    const int tid = threadIdx.x;

    for (int idx = tid; idx < 16 * DEMB; idx += 256) {
        int i = idx >> 9;
        int d = idx & (DEMB - 1);
        int tok = xg[bt0 + i];
        emb_sm[d][i] = tok_emb[(size_t)tok * DEMB + d];
    }
    __syncthreads();

    for (int r = rbase + tid; r < rbase + 1024; r += 256) {
        float acc[16];
#pragma unroll
        for (int i = 0; i < 16; i++) acc[i] = 0.0f;
        for (int s = 0; s < WI_SLOTS; s++) {
            float v = g_wi_val[r * WI_SLOTS + s];
            int   d = g_wi_idx[r * WI_SLOTS + s];
            if (v != 0.0f) {
#pragma unroll
                for (int i0 = 0; i0 < 16; i0 += 4) {
                    float4 e = *reinterpret_cast<const float4*>(&emb_sm[d][i0]);
                    acc[i0+0] += v * e.x; acc[i0+1] += v * e.y;
                    acc[i0+2] += v * e.z; acc[i0+3] += v * e.w;
                }
            }
        }
#pragma unroll
        for (int i = 0; i < 16; i++)
            g_emb_proj[(size_t)(bt0 + i) * RES + r] = acc[i];
    }
}

// ---------------- 4) recurrence (cluster.sync; bank-scheduled gather) ----------------
__global__ void __cluster_dims__(8, 1, 1) __launch_bounds__(256, 1)
recurrence_kernel(const float* __restrict__ a_leak, const float* __restrict__ h0)
{
    __shared__ float hbuf[2][RES];
    cg::cluster_group cl = cg::this_cluster();

    const int tid  = threadIdx.x;
    const int b    = blockIdx.x >> 3;
    const int rank = (int)cl.block_rank();
    const int row  = rank * 256 + tid;

    float wv[WR_SLOTS];
    int   wi[WR_SLOTS];
    const int scnt = g_ws_cnt[row];          // warp-uniform, multiple of 4
#pragma unroll
    for (int s = 0; s < WR_SLOTS; s++) {
        wv[s] = g_ws_val[row * WR_SLOTS + s];
        wi[s] = g_ws_idx[row * WR_SLOTS + s];
    }

    for (int j = tid; j < RES; j += 256) hbuf[0][j] = h0[j];
    const float aL   = a_leak[row];
    float       h_my = h0[row];
    __syncthreads();

    const float* ep_base = g_emb_proj + (size_t)b * TLEN * RES + row;
    float*       hs_base = g_hs       + (size_t)b * TLEN * RES + row;

    float ep = ep_base[0];
    for (int t = 0; t < TLEN; t++) {
        const int cur = t & 1, nxt = cur ^ 1;
        float ep_next = (t + 1 < TLEN) ? ep_base[(size_t)(t + 1) * RES] : 0.0f;
        float a0 = 0.0f, a1 = 0.0f, a2 = 0.0f, a3 = 0.0f;
#pragma unroll
        for (int s = 0; s < WR_SLOTS; s += 4) {
            if (s < scnt) {
                a0 += wv[s + 0] * hbuf[cur][wi[s + 0]];
                a1 += wv[s + 1] * hbuf[cur][wi[s + 1]];
                a2 += wv[s + 2] * hbuf[cur][wi[s + 2]];
                a3 += wv[s + 3] * hbuf[cur][wi[s + 3]];
            }
        }
        float pre = ep + ((a0 + a1) + (a2 + a3));
        pre = fminf(10.0f, fmaxf(-10.0f, pre));
        float hn = (1.0f - aL) * h_my + aL * tanhf(pre);
        h_my = hn;
        ep = ep_next;
        hs_base[(size_t)t * RES] = hn;

#pragma unroll
        for (int p = 0; p < 8; p++) {
            float* dst = cl.map_shared_rank(&hbuf[nxt][row], p);
            *dst = hn;
        }
        cl.sync();
    }
}

// ---------------- 5) proj GEMM fused with fp16 convert (A = Ah only) ----------------
__global__ __launch_bounds__(256) void proj_gemm_kernel(const float* __restrict__ B)
{
    __shared__ float As[8][128];
    __shared__ float Bs[8][128];
    const float* A = g_hs;
    const int tid = threadIdx.x;
    const int m0 = blockIdx.y * 128;
    const int n0 = blockIdx.x * 128;
    const int ty = tid >> 4;
    const int tx = tid & 15;
    const int lrow = tid >> 1;
    const int lk   = (tid & 1) * 4;

    unsigned long long acc[8][4];
#pragma unroll
    for (int i = 0; i < 8; i++)
#pragma unroll
        for (int j = 0; j < 4; j++) acc[i][j] = 0ull;

    for (int k0 = 0; k0 < RES; k0 += 8) {
        float4 av = *reinterpret_cast<const float4*>(A + (size_t)(m0 + lrow) * RES + k0 + lk);
        As[lk+0][lrow] = av.x; As[lk+1][lrow] = av.y;
        As[lk+2][lrow] = av.z; As[lk+3][lrow] = av.w;
        float4 bv = *reinterpret_cast<const float4*>(B + (size_t)(n0 + lrow) * RES + k0 + lk);
        Bs[lk+0][lrow] = bv.x; Bs[lk+1][lrow] = bv.y;
        Bs[lk+2][lrow] = bv.z; Bs[lk+3][lrow] = bv.w;
        __syncthreads();

#pragma unroll
        for (int kk = 0; kk < 8; kk++) {
            float4 a0 = *reinterpret_cast<const float4*>(&As[kk][ty * 8]);
            float4 a1 = *reinterpret_cast<const float4*>(&As[kk][ty * 8 + 4]);
            float4 b0 = *reinterpret_cast<const float4*>(&Bs[kk][tx * 8]);
            float4 b1 = *reinterpret_cast<const float4*>(&Bs[kk][tx * 8 + 4]);
            unsigned long long b2[4] = { pk2(b0.x, b0.y), pk2(b0.z, b0.w),
                                         pk2(b1.x, b1.y), pk2(b1.z, b1.w) };
            float a[8] = { a0.x, a0.y, a0.z, a0.w, a1.x, a1.y, a1.z, a1.w };
#pragma unroll
            for (int i = 0; i < 8; i++) {
                unsigned long long a2 = pk2(a[i], a[i]);
                fma2(acc[i][0], a2, b2[0]);
                fma2(acc[i][1], a2, b2[1]);
                fma2(acc[i][2], a2, b2[2]);
                fma2(acc[i][3], a2, b2[3]);
            }
        }
        __syncthreads();
    }

#pragma unroll
    for (int i = 0; i < 8; i++) {
        int m = m0 + ty * 8 + i;
        __half* arow = g_acat + (size_t)m * KCA;
#pragma unroll
        for (int jp = 0; jp < 4; jp++) {
            float2 v = upk2(acc[i][jp]);
            int k = n0 + tx * 8 + jp * 2;
            __half2 hp;
            hp.x = __float2half_rn(v.x);
            hp.y = __float2half_rn(v.y);
            *reinterpret_cast<__half2*>(arow + k) = hp;
        }
    }
}

// ---------------- 6) convert B to [hi|lo] fp16 (vectorized) ----------------
__global__ __launch_bounds__(256) void convert_b_kernel(const float* __restrict__ src) {
    int idx = blockIdx.x * 256 + threadIdx.x;
    if (idx >= VOCAB_PAD * (ROUT / 8)) return;
    int r  = idx >> 6;
    int k8 = (idx & 63) * 8;
    __half h[8], l[8];
    if (r < VOCAB) {
        const float* s = src + (size_t)r * ROUT + k8;
        float4 v0 = *reinterpret_cast<const float4*>(s);
        float4 v1 = *reinterpret_cast<const float4*>(s + 4);
        float vv[8] = {v0.x, v0.y, v0.z, v0.w, v1.x, v1.y, v1.z, v1.w};
#pragma unroll
        for (int i = 0; i < 8; i++) {
            h[i] = __float2half_rn(vv[i]);
            l[i] = __float2half_rn(vv[i] - __half2float(h[i]));
        }
    } else {
#pragma unroll
        for (int i = 0; i < 8; i++) { h[i] = __float2half_rn(0.0f); l[i] = h[i]; }
    }
    __half* row = g_bcat + (size_t)r * KCB;
    *reinterpret_cast<uint4*>(row + k8)       = *reinterpret_cast<uint4*>(h);
    *reinterpret_cast<uint4*>(row + 512 + k8) = *reinterpret_cast<uint4*>(l);
}

// ---------------- 7) logits GEMM via mma.sync fp16 — 2-product, K-step 64, 3 stages ----
#define KS64    16
#define STAGE2  32768            // A 16KB (128 x 128B) + B 16KB
#define SWZ2(row, c) ((row) * 128 + (((c) ^ ((row) & 7)) * 16))

__global__ __launch_bounds__(256, 2) void logits_mma_kernel(
    const float* __restrict__ bias, float* __restrict__ out)
{
    extern __shared__ __align__(128) char smem[];
    const uint32_t sbase = smem_u32(smem);
    float* bias_sm = reinterpret_cast<float*>(smem + 3 * STAGE2);

    const int tid = threadIdx.x;
    const int wid = tid >> 5;
    const int lane = tid & 31;
    const int m0 = blockIdx.x * 128;       // m fast -> wave shares B in L2
    const int n0 = blockIdx.y * 128;
    const int wm = (wid & 3) * 32;
    const int wn = (wid >> 2) * 64;

    if (tid < 128) {
        int n = n0 + tid;
        bias_sm[tid] = (n < VOCAB) ? bias[n] : 0.0f;
    }

    const char* Ab = (const char*)g_acat + (size_t)m0 * (KCA * 2);
    const char* Bb = (const char*)g_bcat + (size_t)n0 * (KCB * 2);

    auto load_stage = [&](int j, int slot) {
        const size_t ka = (size_t)(j & 7) * 128;    // 64 fp16 = 128 bytes
        const size_t kb = (size_t)j * 128;
        const uint32_t sa = sbase + slot * STAGE2;
        const uint32_t sb = sa + 16384;
#pragma unroll
        for (int i = 0; i < 4; i++) {
            int c = tid + i * 256;
            int r = c >> 3, col = c & 7;
            cp16(sa + SWZ2(r, col), Ab + (size_t)r * (KCA * 2) + ka + col * 16);
        }
#pragma unroll
        for (int i = 0; i < 4; i++) {
            int c = tid + i * 256;
            int r = c >> 3, col = c & 7;
            cp16(sb + SWZ2(r, col), Bb + (size_t)r * (KCB * 2) + kb + col * 16);
        }
    };

    int rowA[2], swA[2];
#pragma unroll
    for (int mf = 0; mf < 2; mf++) {
        rowA[mf] = wm + mf * 16 + (lane & 7) + ((lane >> 3) & 1) * 8;
        swA[mf]  = rowA[mf] & 7;
    }
    const int caddA = lane >> 4;
    int rowB[4], swB[4];
#pragma unroll
    for (int nb = 0; nb < 4; nb++) {
        rowB[nb] = wn + nb * 16 + (lane & 7) + (lane >> 4) * 8;
        swB[nb]  = rowB[nb] & 7;
    }
    const int caddB = (lane >> 3) & 1;

    float acc[2][8][4];
#pragma unroll
    for (int mf = 0; mf < 2; mf++)
#pragma unroll
        for (int nf = 0; nf < 8; nf++)
#pragma unroll
            for (int i = 0; i < 4; i++) acc[mf][nf][i] = 0.0f;

    load_stage(0, 0); cp_commit();
    load_stage(1, 1); cp_commit();

    int slot = 0;
    for (int j = 0; j < KS64; j++) {
        cp_wait<1>();
        __syncthreads();
        if (j + 2 < KS64) {
            int s2 = j + 2 - ((j + 2) / 3) * 3;     // (j+2) % 3
            load_stage(j + 2, s2);
        }
        cp_commit();

        const uint32_t sa = sbase + slot * STAGE2;
        const uint32_t sb = sa + 16384;
#pragma unroll
        for (int kk = 0; kk < 4; kk++) {
            uint32_t a[2][4], b[4][4];
#pragma unroll
            for (int mf = 0; mf < 2; mf++) {
                int c = kk * 2 + caddA;
                ldsm4(a[mf], sa + rowA[mf] * 128 + ((c ^ swA[mf]) * 16));
            }
#pragma unroll
            for (int nb = 0; nb < 4; nb++) {
                int c = kk * 2 + caddB;
                ldsm4(b[nb], sb + rowB[nb] * 128 + ((c ^ swB[nb]) * 16));
            }
#pragma unroll
            for (int mf = 0; mf < 2; mf++)
#pragma unroll
                for (int nf = 0; nf < 8; nf++)
                    mma16816(acc[mf][nf], a[mf], b[nf >> 1][(nf & 1) * 2],
                             b[nf >> 1][(nf & 1) * 2 + 1]);
        }
        if (++slot == 3) slot = 0;
    }

    // epilogue: scalar stores (VOCAB odd -> rows alternate 8B alignment)
#pragma unroll
    for (int mf = 0; mf < 2; mf++) {
        int mrow = m0 + wm + mf * 16 + (lane >> 2);
        float* crow0 = out + (size_t)mrow * VOCAB;
        float* crow1 = out + (size_t)(mrow + 8) * VOCAB;
#pragma unroll
        for (int nf = 0; nf < 8; nf++) {
            int nl = wn + nf * 8 + (lane & 3) * 2;
            int n = n0 + nl;
            if (n < VOCAB) {
                crow0[n] = acc[mf][nf][0] + bias_sm[nl];
                crow1[n] = acc[mf][nf][2] + bias_sm[nl];
            }
            if (n + 1 < VOCAB) {
                crow0[n + 1] = acc[mf][nf][1] + bias_sm[nl + 1];
                crow1[n + 1] = acc[mf][nf][3] + bias_sm[nl + 1];
            }
        }
    }
}

// ---------------- host launcher ----------------
extern "C" void kernel_launch(void* const* d_in, const int* in_sizes, int n_in,
                              void* d_out, int out_size)
{
    const int*   x    = (const int*)  d_in[0];
    const float* temb = (const float*)d_in[1];
    const float* Win  = (const float*)d_in[2];
    const float* Wrec = (const float*)d_in[3];
    const float* a    = (const float*)d_in[4];
    const float* Wb   = (const float*)d_in[5];
    const float* Wa   = (const float*)d_in[6];
    const float* bias = (const float*)d_in[7];
    const float* h0   = (const float*)d_in[8];
    float* out = (float*)d_out;

    // preprocessing (independent of recurrence)
    sparsify_wrec_kernel<<<256, 256>>>(Wrec);
    schedule_wrec_kernel<<<8, 256>>>();
    sparsify_win_kernel<<<256, 256>>>(Win);
    convert_b_kernel<<<(VOCAB_PAD * (ROUT / 8) + 255) / 256, 256>>>(Wa);

    embed_proj_kernel<<<dim3(BT / 16, 2), 256>>>(x, temb);
    recurrence_kernel<<<64, 256>>>(a, h0);

    // proj = hs @ Wb^T fused with fp16 convert -> g_acat (Ah)
    proj_gemm_kernel<<<dim3(ROUT / 128, BT / 128), 256>>>(Wb);

    // logits = Ah*(Bh+Bl) fp16 2-product GEMM + bias (K-step 64, 3 stages)
    const int smem_bytes = 3 * STAGE2 + 512;   // 98816
    cudaFuncSetAttribute(logits_mma_kernel,
                         cudaFuncAttributeMaxDynamicSharedMemorySize, smem_bytes);
    logits_mma_kernel<<<dim3(BT / 128, VOCAB_PAD / 128), 256, smem_bytes>>>(bias, out);
}

// round 12
// speedup vs baseline: 1.2223x; 1.2223x over previous
#include <cuda_runtime.h>
#include <cuda_bf16.h>
#include <cuda_fp16.h>
#include <cooperative_groups.h>
#include <cstdint>

namespace cg = cooperative_groups;

// ---------------- problem constants ----------------
#define VOCAB   50257
#define VOCAB_PAD 50432           // 394 * 128
#define DEMB    512
#define RES     2048
#define ROUT    512
#define BATCH   8
#define TLEN    256
#define BT      (BATCH*TLEN)      // 2048
#define KCA     512               // stored A: [Ah]           (fp16)
#define KCB     1024              // stored B: [Bh | Bl]      (fp16)
#define WR_SLOTS 64
#define WI_SLOTS 32
#define FULLW   0xffffffffu

// ---------------- device scratch (no allocs allowed) ----------------
__device__ float g_emb_proj[BT * RES];
__device__ float g_hs      [BT * RES];
__device__ float g_wr_val  [RES * WR_SLOTS];
__device__ int   g_wr_idx  [RES * WR_SLOTS];
__device__ int   g_wr_cnt  [RES];
__device__ float g_wi_val  [RES * WI_SLOTS];
__device__ int   g_wi_idx  [RES * WI_SLOTS];
__device__ __half g_acat[BT * KCA];            // 2.1 MB
__device__ __half g_bcat[VOCAB_PAD * KCB];     // 103 MB

// ---------------- small PTX helpers (sm_80-compatible only) ----------------
__device__ __forceinline__ uint32_t smem_u32(const void* p) {
    uint32_t a;
    asm("{ .reg .u64 t; cvta.to.shared.u64 t, %1; cvt.u32.u64 %0, t; }" : "=r"(a) : "l"(p));
    return a;
}
__device__ __forceinline__ void cp16(uint32_t saddr, const void* g) {
    asm volatile("cp.async.cg.shared.global [%0], [%1], 16;" :: "r"(saddr), "l"(g) : "memory");
}
__device__ __forceinline__ void cp_commit() { asm volatile("cp.async.commit_group;" ::: "memory"); }
template<int N> __device__ __forceinline__ void cp_wait() {
    asm volatile("cp.async.wait_group %0;" :: "n"(N) : "memory");
}
__device__ __forceinline__ void ldsm4(uint32_t r[4], uint32_t addr) {
    asm volatile("ldmatrix.sync.aligned.m8n8.x4.shared.b16 {%0,%1,%2,%3}, [%4];"
                 : "=r"(r[0]), "=r"(r[1]), "=r"(r[2]), "=r"(r[3]) : "r"(addr));
}
__device__ __forceinline__ void mma16816(float c[4], const uint32_t a[4],
                                         uint32_t b0, uint32_t b1) {
    asm volatile("mma.sync.aligned.m16n8k16.row.col.f32.f16.f16.f32 "
                 "{%0,%1,%2,%3}, {%4,%5,%6,%7}, {%8,%9}, {%0,%1,%2,%3};"
                 : "+f"(c[0]), "+f"(c[1]), "+f"(c[2]), "+f"(c[3])
                 : "r"(a[0]), "r"(a[1]), "r"(a[2]), "r"(a[3]), "r"(b0), "r"(b1));
}

// ---------------- f32x2 packed-FMA helpers (proj GEMM) ----------------
__device__ __forceinline__ unsigned long long pk2(float x, float y) {
    unsigned long long r;
    asm("mov.b64 %0, {%1, %2};" : "=l"(r) : "f"(x), "f"(y));
    return r;
}
__device__ __forceinline__ void fma2(unsigned long long& d, unsigned long long a, unsigned long long b) {
    asm("fma.rn.f32x2 %0, %1, %2, %0;" : "+l"(d) : "l"(a), "l"(b));
}
__device__ __forceinline__ float2 upk2(unsigned long long v) {
    float2 r;
    asm("mov.b64 {%0, %1}, %2;" : "=f"(r.x), "=f"(r.y) : "l"(v));
    return r;
}

// ---------------- 1) sparsify W_rec ----------------
__global__ void sparsify_wrec_kernel(const float* __restrict__ W) {
    int warp = blockIdx.x * (blockDim.x >> 5) + (threadIdx.x >> 5);
    int lane = threadIdx.x & 31;
    if (warp >= RES) return;
    const float* row = W + (size_t)warp * RES;
    int base = 0;
    for (int j0 = 0; j0 < RES; j0 += 32) {
        float v = row[j0 + lane];
        unsigned m = __ballot_sync(FULLW, v != 0.0f);
        int pref = __popc(m & ((1u << lane) - 1u));
        if (v != 0.0f) {
            int pos = base + pref;
            if (pos < WR_SLOTS) {
                g_wr_val[warp * WR_SLOTS + pos] = v;
                g_wr_idx[warp * WR_SLOTS + pos] = j0 + lane;
            }
        }
        base += __popc(m);
    }
    int bb = base < WR_SLOTS ? base : WR_SLOTS;
    if (lane == 0) g_wr_cnt[warp] = bb;
    for (int s = bb + lane; s < WR_SLOTS; s += 32) {
        g_wr_val[warp * WR_SLOTS + s] = 0.0f;
        g_wr_idx[warp * WR_SLOTS + s] = 0;
    }
}

// ---------------- 2) sparsify W_in ----------------
__global__ void sparsify_win_kernel(const float* __restrict__ W) {
    int col  = blockIdx.x * (blockDim.x >> 5) + (threadIdx.x >> 5);
    int lane = threadIdx.x & 31;
    if (col >= RES) return;
    int base = 0;
    for (int d0 = 0; d0 < DEMB; d0 += 32) {
        float v = W[(size_t)(d0 + lane) * RES + col];
        unsigned m = __ballot_sync(FULLW, v != 0.0f);
        int pref = __popc(m & ((1u << lane) - 1u));
        if (v != 0.0f) {
            int pos = base + pref;
            if (pos < WI_SLOTS) {
                g_wi_val[col * WI_SLOTS + pos] = v;
                g_wi_idx[col * WI_SLOTS + pos] = d0 + lane;
            }
        }
        base += __popc(m);
    }
    int bb = base < WI_SLOTS ? base : WI_SLOTS;
    for (int s = bb + lane; s < WI_SLOTS; s += 32) {
        g_wi_val[col * WI_SLOTS + s] = 0.0f;
        g_wi_idx[col * WI_SLOTS + s] = 0;
    }
}

// ---------------- 3) embed + sparse input projection (RES split 4-way) ----------------
__global__ __launch_bounds__(256) void embed_proj_kernel(
    const int* __restrict__ xg, const float* __restrict__ tok_emb)
{
    __shared__ __align__(16) float emb_sm[DEMB][20];
    const int bt0 = blockIdx.x * 16;
    const int rbase = blockIdx.y * 512;
    const int tid = threadIdx.x;

    for (int idx = tid; idx < 16 * DEMB; idx += 256) {
        int i = idx >> 9;
        int d = idx & (DEMB - 1);
        int tok = xg[bt0 + i];
        emb_sm[d][i] = tok_emb[(size_t)tok * DEMB + d];
    }
    __syncthreads();

    for (int r = rbase + tid; r < rbase + 512; r += 256) {
        float acc[16];
#pragma unroll
        for (int i = 0; i < 16; i++) acc[i] = 0.0f;
        for (int s = 0; s < WI_SLOTS; s++) {
            float v = g_wi_val[r * WI_SLOTS + s];
            int   d = g_wi_idx[r * WI_SLOTS + s];
            if (v != 0.0f) {
#pragma unroll
                for (int i0 = 0; i0 < 16; i0 += 4) {
                    float4 e = *reinterpret_cast<const float4*>(&emb_sm[d][i0]);
                    acc[i0+0] += v * e.x; acc[i0+1] += v * e.y;
                    acc[i0+2] += v * e.z; acc[i0+3] += v * e.w;
                }
            }
        }
#pragma unroll
        for (int i = 0; i < 16; i++)
            g_emb_proj[(size_t)(bt0 + i) * RES + r] = acc[i];
    }
}

// ---------------- 4) recurrence (R10 form: cluster.sync + prefetch + 4-way acc) ---------
__global__ void __cluster_dims__(8, 1, 1) __launch_bounds__(256, 1)
recurrence_kernel(const float* __restrict__ a_leak, const float* __restrict__ h0)
{
    __shared__ float hbuf[2][RES];
    cg::cluster_group cl = cg::this_cluster();

    const int tid  = threadIdx.x;
    const int b    = blockIdx.x >> 3;
    const int rank = (int)cl.block_rank();
    const int row  = rank * 256 + tid;

    float wv[WR_SLOTS];
    int   wi[WR_SLOTS];
    const int cnt = g_wr_cnt[row];
#pragma unroll
    for (int s = 0; s < WR_SLOTS; s++) {
        wv[s] = g_wr_val[row * WR_SLOTS + s];
        wi[s] = g_wr_idx[row * WR_SLOTS + s];
    }

    for (int j = tid; j < RES; j += 256) hbuf[0][j] = h0[j];
    const float aL   = a_leak[row];
    float       h_my = h0[row];
    __syncthreads();

    const float* ep_base = g_emb_proj + (size_t)b * TLEN * RES + row;
    float*       hs_base = g_hs       + (size_t)b * TLEN * RES + row;

    float ep = ep_base[0];
    for (int t = 0; t < TLEN; t++) {
        const int cur = t & 1, nxt = cur ^ 1;
        float ep_next = (t + 1 < TLEN) ? ep_base[(size_t)(t + 1) * RES] : 0.0f;
        float a0 = 0.0f, a1 = 0.0f, a2 = 0.0f, a3 = 0.0f;
#pragma unroll
        for (int s = 0; s < WR_SLOTS; s += 4) {
            if (s + 0 < cnt) a0 += wv[s + 0] * hbuf[cur][wi[s + 0]];
            if (s + 1 < cnt) a1 += wv[s + 1] * hbuf[cur][wi[s + 1]];
            if (s + 2 < cnt) a2 += wv[s + 2] * hbuf[cur][wi[s + 2]];
            if (s + 3 < cnt) a3 += wv[s + 3] * hbuf[cur][wi[s + 3]];
        }
        float pre = ep + ((a0 + a1) + (a2 + a3));
        pre = fminf(10.0f, fmaxf(-10.0f, pre));
        float hn = (1.0f - aL) * h_my + aL * tanhf(pre);
        h_my = hn;
        ep = ep_next;
        hs_base[(size_t)t * RES] = hn;

#pragma unroll
        for (int p = 0; p < 8; p++) {
            float* dst = cl.map_shared_rank(&hbuf[nxt][row], p);
            *dst = hn;
        }
        cl.sync();
    }
}

// ---------------- 5) proj GEMM (tile 128m x 64n, 128 CTAs) fused fp16 convert ----------
__global__ __launch_bounds__(256) void proj_gemm_kernel(const float* __restrict__ B)
{
    __shared__ float As[8][128];
    __shared__ float Bs[8][64];
    const float* A = g_hs;
    const int tid = threadIdx.x;
    const int m0 = blockIdx.y * 128;
    const int n0 = blockIdx.x * 64;
    const int ty = tid >> 4;          // 0..15 -> 8 m each
    const int tx = tid & 15;          // 0..15 -> 4 n each
    const int lrow = tid >> 1;        // A loader row 0..127
    const int lk   = (tid & 1) * 4;

    unsigned long long acc[8][2];
#pragma unroll
    for (int i = 0; i < 8; i++) { acc[i][0] = 0ull; acc[i][1] = 0ull; }

    for (int k0 = 0; k0 < RES; k0 += 8) {
        float4 av = *reinterpret_cast<const float4*>(A + (size_t)(m0 + lrow) * RES + k0 + lk);
        As[lk+0][lrow] = av.x; As[lk+1][lrow] = av.y;
        As[lk+2][lrow] = av.z; As[lk+3][lrow] = av.w;
        if (tid < 128) {
            float4 bv = *reinterpret_cast<const float4*>(B + (size_t)(n0 + lrow) * RES + k0 + lk);
            Bs[lk+0][lrow] = bv.x; Bs[lk+1][lrow] = bv.y;
            Bs[lk+2][lrow] = bv.z; Bs[lk+3][lrow] = bv.w;
        }
        __syncthreads();

#pragma unroll
        for (int kk = 0; kk < 8; kk++) {
            float4 a0 = *reinterpret_cast<const float4*>(&As[kk][ty * 8]);
            float4 a1 = *reinterpret_cast<const float4*>(&As[kk][ty * 8 + 4]);
            float4 b0 = *reinterpret_cast<const float4*>(&Bs[kk][tx * 4]);
            unsigned long long b2[2] = { pk2(b0.x, b0.y), pk2(b0.z, b0.w) };
            float a[8] = { a0.x, a0.y, a0.z, a0.w, a1.x, a1.y, a1.z, a1.w };
#pragma unroll
            for (int i = 0; i < 8; i++) {
                unsigned long long a2 = pk2(a[i], a[i]);
                fma2(acc[i][0], a2, b2[0]);
                fma2(acc[i][1], a2, b2[1]);
            }
        }
        __syncthreads();
    }

    // fused epilogue: round proj to fp16 (Ah), store packed pairs
#pragma unroll
    for (int i = 0; i < 8; i++) {
        int m = m0 + ty * 8 + i;
        __half* arow = g_acat + (size_t)m * KCA;
#pragma unroll
        for (int jp = 0; jp < 2; jp++) {
            float2 v = upk2(acc[i][jp]);
            int k = n0 + tx * 4 + jp * 2;
            __half2 hp;
            hp.x = __float2half_rn(v.x);
            hp.y = __float2half_rn(v.y);
            *reinterpret_cast<__half2*>(arow + k) = hp;
        }
    }
}

// ---------------- 6) convert B to [hi|lo] fp16 (vectorized) ----------------
__global__ __launch_bounds__(256) void convert_b_kernel(const float* __restrict__ src) {
    int idx = blockIdx.x * 256 + threadIdx.x;
    if (idx >= VOCAB_PAD * (ROUT / 8)) return;
    int r  = idx >> 6;
    int k8 = (idx & 63) * 8;
    __half h[8], l[8];
    if (r < VOCAB) {
        const float* s = src + (size_t)r * ROUT + k8;
        float4 v0 = *reinterpret_cast<const float4*>(s);
        float4 v1 = *reinterpret_cast<const float4*>(s + 4);
        float vv[8] = {v0.x, v0.y, v0.z, v0.w, v1.x, v1.y, v1.z, v1.w};
#pragma unroll
        for (int i = 0; i < 8; i++) {
            h[i] = __float2half_rn(vv[i]);
            l[i] = __float2half_rn(vv[i] - __half2float(h[i]));
        }
    } else {
#pragma unroll
        for (int i = 0; i < 8; i++) { h[i] = __float2half_rn(0.0f); l[i] = h[i]; }
    }
    __half* row = g_bcat + (size_t)r * KCB;
    *reinterpret_cast<uint4*>(row + k8)       = *reinterpret_cast<uint4*>(h);
    *reinterpret_cast<uint4*>(row + 512 + k8) = *reinterpret_cast<uint4*>(l);
}

// ---------------- 7) logits GEMM via mma.sync fp16 — 2-product, K-step 64, 3 stages ----
// virtual j=0..15 (64 K each): A chunk ak = j & 7   (Ah repeated)
//                              B chunk bk = j       ([Bh | Bl])
#define KS64    16
#define STAGE2  32768            // A 16KB (128 x 128B) + B 16KB
#define SWZ2(row, c) ((row) * 128 + (((c) ^ ((row) & 7)) * 16))

__global__ __launch_bounds__(256, 2) void logits_mma_kernel(
    const float* __restrict__ bias, float* __restrict__ out)
{
    extern __shared__ __align__(128) char smem[];
    const uint32_t sbase = smem_u32(smem);
    float* bias_sm = reinterpret_cast<float*>(smem + 3 * STAGE2);

    const int tid = threadIdx.x;
    const int wid = tid >> 5;
    const int lane = tid & 31;
    const int m0 = blockIdx.x * 128;       // m fast -> wave shares B in L2
    const int n0 = blockIdx.y * 128;
    const int wm = (wid & 3) * 32;
    const int wn = (wid >> 2) * 64;

    if (tid < 128) {
        int n = n0 + tid;
        bias_sm[tid] = (n < VOCAB) ? bias[n] : 0.0f;
    }

    const char* Ab = (const char*)g_acat + (size_t)m0 * (KCA * 2);
    const char* Bb = (const char*)g_bcat + (size_t)n0 * (KCB * 2);

    auto load_stage = [&](int j, int slot) {
        const size_t ka = (size_t)(j & 7) * 128;    // 64 fp16 = 128 bytes
        const size_t kb = (size_t)j * 128;
        const uint32_t sa = sbase + slot * STAGE2;
        const uint32_t sb = sa + 16384;
#pragma unroll
        for (int i = 0; i < 4; i++) {
            int c = tid + i * 256;
            int r = c >> 3, col = c & 7;
            cp16(sa + SWZ2(r, col), Ab + (size_t)r * (KCA * 2) + ka + col * 16);
        }
#pragma unroll
        for (int i = 0; i < 4; i++) {
            int c = tid + i * 256;
            int r = c >> 3, col = c & 7;
            cp16(sb + SWZ2(r, col), Bb + (size_t)r * (KCB * 2) + kb + col * 16);
        }
    };

    int rowA[2], swA[2];
#pragma unroll
    for (int mf = 0; mf < 2; mf++) {
        rowA[mf] = wm + mf * 16 + (lane & 7) + ((lane >> 3) & 1) * 8;
        swA[mf]  = rowA[mf] & 7;
    }
    const int caddA = lane >> 4;
    int rowB[4], swB[4];
#pragma unroll
    for (int nb = 0; nb < 4; nb++) {
        rowB[nb] = wn + nb * 16 + (lane & 7) + (lane >> 4) * 8;
        swB[nb]  = rowB[nb] & 7;
    }
    const int caddB = (lane >> 3) & 1;

    float acc[2][8][4];
#pragma unroll
    for (int mf = 0; mf < 2; mf++)
#pragma unroll
        for (int nf = 0; nf < 8; nf++)
#pragma unroll
            for (int i = 0; i < 4; i++) acc[mf][nf][i] = 0.0f;

    load_stage(0, 0); cp_commit();
    load_stage(1, 1); cp_commit();

    int slot = 0;
    for (int j = 0; j < KS64; j++) {
        cp_wait<1>();
        __syncthreads();
        if (j + 2 < KS64) {
            int s2 = j + 2 - ((j + 2) / 3) * 3;     // (j+2) % 3
            load_stage(j + 2, s2);
        }
        cp_commit();

        const uint32_t sa = sbase + slot * STAGE2;
        const uint32_t sb = sa + 16384;
#pragma unroll
        for (int kk = 0; kk < 4; kk++) {
            uint32_t a[2][4], b[4][4];
#pragma unroll
            for (int mf = 0; mf < 2; mf++) {
                int c = kk * 2 + caddA;
                ldsm4(a[mf], sa + rowA[mf] * 128 + ((c ^ swA[mf]) * 16));
            }
#pragma unroll
            for (int nb = 0; nb < 4; nb++) {
                int c = kk * 2 + caddB;
                ldsm4(b[nb], sb + rowB[nb] * 128 + ((c ^ swB[nb]) * 16));
            }
#pragma unroll
            for (int mf = 0; mf < 2; mf++)
#pragma unroll
                for (int nf = 0; nf < 8; nf++)
                    mma16816(acc[mf][nf], a[mf], b[nf >> 1][(nf & 1) * 2],
                             b[nf >> 1][(nf & 1) * 2 + 1]);
        }
        if (++slot == 3) slot = 0;
    }

    // epilogue: scalar stores (VOCAB odd -> rows alternate 8B alignment)
#pragma unroll
    for (int mf = 0; mf < 2; mf++) {
        int mrow = m0 + wm + mf * 16 + (lane >> 2);
        float* crow0 = out + (size_t)mrow * VOCAB;
        float* crow1 = out + (size_t)(mrow + 8) * VOCAB;
#pragma unroll
        for (int nf = 0; nf < 8; nf++) {
            int nl = wn + nf * 8 + (lane & 3) * 2;
            int n = n0 + nl;
            if (n < VOCAB) {
                crow0[n] = acc[mf][nf][0] + bias_sm[nl];
                crow1[n] = acc[mf][nf][2] + bias_sm[nl];
            }
            if (n + 1 < VOCAB) {
                crow0[n + 1] = acc[mf][nf][1] + bias_sm[nl + 1];
                crow1[n + 1] = acc[mf][nf][3] + bias_sm[nl + 1];
            }
        }
    }
}

// ---------------- host launcher ----------------
extern "C" void kernel_launch(void* const* d_in, const int* in_sizes, int n_in,
                              void* d_out, int out_size)
{
    const int*   x    = (const int*)  d_in[0];
    const float* temb = (const float*)d_in[1];
    const float* Win  = (const float*)d_in[2];
    const float* Wrec = (const float*)d_in[3];
    const float* a    = (const float*)d_in[4];
    const float* Wb   = (const float*)d_in[5];
    const float* Wa   = (const float*)d_in[6];
    const float* bias = (const float*)d_in[7];
    const float* h0   = (const float*)d_in[8];
    float* out = (float*)d_out;

    // preprocessing (independent of recurrence)
    sparsify_wrec_kernel<<<256, 256>>>(Wrec);
    sparsify_win_kernel<<<256, 256>>>(Win);
    convert_b_kernel<<<(VOCAB_PAD * (ROUT / 8) + 255) / 256, 256>>>(Wa);

    embed_proj_kernel<<<dim3(BT / 16, 4), 256>>>(x, temb);
    recurrence_kernel<<<64, 256>>>(a, h0);

    // proj = hs @ Wb^T fused with fp16 convert -> g_acat (Ah), 128 CTAs
    proj_gemm_kernel<<<dim3(ROUT / 64, BT / 128), 256>>>(Wb);

    // logits = Ah*(Bh+Bl) fp16 2-product GEMM + bias (K-step 64, 3 stages)
    const int smem_bytes = 3 * STAGE2 + 512;   // 98816
    cudaFuncSetAttribute(logits_mma_kernel,
                         cudaFuncAttributeMaxDynamicSharedMemorySize, smem_bytes);
    logits_mma_kernel<<<dim3(BT / 128, VOCAB_PAD / 128), 256, smem_bytes>>>(bias, out);
}

// round 13
// speedup vs baseline: 1.4795x; 1.2104x over previous
#include <cuda_runtime.h>
#include <cuda_bf16.h>
#include <cuda_fp16.h>
#include <cooperative_groups.h>
#include <cstdint>

namespace cg = cooperative_groups;

// ---------------- problem constants ----------------
#define VOCAB   50257
#define VOCAB_PAD 50432           // 394 * 128
#define DEMB    512
#define RES     2048
#define ROUT    512
#define BATCH   8
#define TLEN    256
#define BT      (BATCH*TLEN)      // 2048
#define KCA     512               // stored A: [Ah]  (fp16)
#define KCB     512               // stored B: [Bh]  (fp16, single product)
#define WR_SLOTS 64
#define WI_SLOTS 32
#define FULLW   0xffffffffu

// ---------------- device scratch (no allocs allowed) ----------------
__device__ float g_emb_proj[BT * RES];
__device__ float g_hs      [BT * RES];
__device__ float g_wr_val  [RES * WR_SLOTS];
__device__ int   g_wr_idx  [RES * WR_SLOTS];
__device__ int   g_wr_cnt  [RES];
__device__ float g_wi_val  [RES * WI_SLOTS];
__device__ int   g_wi_idx  [RES * WI_SLOTS];
__device__ __half g_acat[BT * KCA];            // 2.1 MB
__device__ __half g_bcat[VOCAB_PAD * KCB];     // 51.6 MB

// ---------------- small PTX helpers (sm_80-compatible only) ----------------
__device__ __forceinline__ uint32_t smem_u32(const void* p) {
    uint32_t a;
    asm("{ .reg .u64 t; cvta.to.shared.u64 t, %1; cvt.u32.u64 %0, t; }" : "=r"(a) : "l"(p));
    return a;
}
__device__ __forceinline__ void cp16(uint32_t saddr, const void* g) {
    asm volatile("cp.async.cg.shared.global [%0], [%1], 16;" :: "r"(saddr), "l"(g) : "memory");
}
__device__ __forceinline__ void cp_commit() { asm volatile("cp.async.commit_group;" ::: "memory"); }
template<int N> __device__ __forceinline__ void cp_wait() {
    asm volatile("cp.async.wait_group %0;" :: "n"(N) : "memory");
}
__device__ __forceinline__ void ldsm4(uint32_t r[4], uint32_t addr) {
    asm volatile("ldmatrix.sync.aligned.m8n8.x4.shared.b16 {%0,%1,%2,%3}, [%4];"
                 : "=r"(r[0]), "=r"(r[1]), "=r"(r[2]), "=r"(r[3]) : "r"(addr));
}
__device__ __forceinline__ void mma16816(float c[4], const uint32_t a[4],
                                         uint32_t b0, uint32_t b1) {
    asm volatile("mma.sync.aligned.m16n8k16.row.col.f32.f16.f16.f32 "
                 "{%0,%1,%2,%3}, {%4,%5,%6,%7}, {%8,%9}, {%0,%1,%2,%3};"
                 : "+f"(c[0]), "+f"(c[1]), "+f"(c[2]), "+f"(c[3])
                 : "r"(a[0]), "r"(a[1]), "r"(a[2]), "r"(a[3]), "r"(b0), "r"(b1));
}

// ---------------- f32x2 packed-FMA helpers (proj GEMM) ----------------
__device__ __forceinline__ unsigned long long pk2(float x, float y) {
    unsigned long long r;
    asm("mov.b64 %0, {%1, %2};" : "=l"(r) : "f"(x), "f"(y));
    return r;
}
__device__ __forceinline__ void fma2(unsigned long long& d, unsigned long long a, unsigned long long b) {
    asm("fma.rn.f32x2 %0, %1, %2, %0;" : "+l"(d) : "l"(a), "l"(b));
}
__device__ __forceinline__ float2 upk2(unsigned long long v) {
    float2 r;
    asm("mov.b64 {%0, %1}, %2;" : "=f"(r.x), "=f"(r.y) : "l"(v));
    return r;
}

// ---------------- 1) sparsify W_rec ----------------
__global__ void sparsify_wrec_kernel(const float* __restrict__ W) {
    int warp = blockIdx.x * (blockDim.x >> 5) + (threadIdx.x >> 5);
    int lane = threadIdx.x & 31;
    if (warp >= RES) return;
    const float* row = W + (size_t)warp * RES;
    int base = 0;
    for (int j0 = 0; j0 < RES; j0 += 32) {
        float v = row[j0 + lane];
        unsigned m = __ballot_sync(FULLW, v != 0.0f);
        int pref = __popc(m & ((1u << lane) - 1u));
        if (v != 0.0f) {
            int pos = base + pref;
            if (pos < WR_SLOTS) {
                g_wr_val[warp * WR_SLOTS + pos] = v;
                g_wr_idx[warp * WR_SLOTS + pos] = j0 + lane;
            }
        }
        base += __popc(m);
    }
    int bb = base < WR_SLOTS ? base : WR_SLOTS;
    if (lane == 0) g_wr_cnt[warp] = bb;
    for (int s = bb + lane; s < WR_SLOTS; s += 32) {
        g_wr_val[warp * WR_SLOTS + s] = 0.0f;
        g_wr_idx[warp * WR_SLOTS + s] = 0;
    }
}

// ---------------- 2) sparsify W_in ----------------
__global__ void sparsify_win_kernel(const float* __restrict__ W) {
    int col  = blockIdx.x * (blockDim.x >> 5) + (threadIdx.x >> 5);
    int lane = threadIdx.x & 31;
    if (col >= RES) return;
    int base = 0;
    for (int d0 = 0; d0 < DEMB; d0 += 32) {
        float v = W[(size_t)(d0 + lane) * RES + col];
        unsigned m = __ballot_sync(FULLW, v != 0.0f);
        int pref = __popc(m & ((1u << lane) - 1u));
        if (v != 0.0f) {
            int pos = base + pref;
            if (pos < WI_SLOTS) {
                g_wi_val[col * WI_SLOTS + pos] = v;
                g_wi_idx[col * WI_SLOTS + pos] = d0 + lane;
            }
        }
        base += __popc(m);
    }
    int bb = base < WI_SLOTS ? base : WI_SLOTS;
    for (int s = bb + lane; s < WI_SLOTS; s += 32) {
        g_wi_val[col * WI_SLOTS + s] = 0.0f;
        g_wi_idx[col * WI_SLOTS + s] = 0;
    }
}

// ---------------- 3) embed + sparse input projection (RES split 4-way) ----------------
__global__ __launch_bounds__(256) void embed_proj_kernel(
    const int* __restrict__ xg, const float* __restrict__ tok_emb)
{
    __shared__ __align__(16) float emb_sm[DEMB][20];
    const int bt0 = blockIdx.x * 16;
    const int rbase = blockIdx.y * 512;
    const int tid = threadIdx.x;

    for (int idx = tid; idx < 16 * DEMB; idx += 256) {
        int i = idx >> 9;
        int d = idx & (DEMB - 1);
        int tok = xg[bt0 + i];
        emb_sm[d][i] = tok_emb[(size_t)tok * DEMB + d];
    }
    __syncthreads();

    for (int r = rbase + tid; r < rbase + 512; r += 256) {
        float acc[16];
#pragma unroll
        for (int i = 0; i < 16; i++) acc[i] = 0.0f;
        for (int s = 0; s < WI_SLOTS; s++) {
            float v = g_wi_val[r * WI_SLOTS + s];
            int   d = g_wi_idx[r * WI_SLOTS + s];
            if (v != 0.0f) {
#pragma unroll
                for (int i0 = 0; i0 < 16; i0 += 4) {
                    float4 e = *reinterpret_cast<const float4*>(&emb_sm[d][i0]);
                    acc[i0+0] += v * e.x; acc[i0+1] += v * e.y;
                    acc[i0+2] += v * e.z; acc[i0+3] += v * e.w;
                }
            }
        }
#pragma unroll
        for (int i = 0; i < 16; i++)
            g_emb_proj[(size_t)(bt0 + i) * RES + r] = acc[i];
    }
}

// ---------------- 4) recurrence (R10 form: cluster.sync + prefetch + 4-way acc) ---------
__global__ void __cluster_dims__(8, 1, 1) __launch_bounds__(256, 1)
recurrence_kernel(const float* __restrict__ a_leak, const float* __restrict__ h0)
{
    __shared__ float hbuf[2][RES];
    cg::cluster_group cl = cg::this_cluster();

    const int tid  = threadIdx.x;
    const int b    = blockIdx.x >> 3;
    const int rank = (int)cl.block_rank();
    const int row  = rank * 256 + tid;

    float wv[WR_SLOTS];
    int   wi[WR_SLOTS];
    const int cnt = g_wr_cnt[row];
#pragma unroll
    for (int s = 0; s < WR_SLOTS; s++) {
        wv[s] = g_wr_val[row * WR_SLOTS + s];
        wi[s] = g_wr_idx[row * WR_SLOTS + s];
    }

    for (int j = tid; j < RES; j += 256) hbuf[0][j] = h0[j];
    const float aL   = a_leak[row];
    float       h_my = h0[row];
    __syncthreads();

    const float* ep_base = g_emb_proj + (size_t)b * TLEN * RES + row;
    float*       hs_base = g_hs       + (size_t)b * TLEN * RES + row;

    float ep = ep_base[0];
    for (int t = 0; t < TLEN; t++) {
        const int cur = t & 1, nxt = cur ^ 1;
        float ep_next = (t + 1 < TLEN) ? ep_base[(size_t)(t + 1) * RES] : 0.0f;
        float a0 = 0.0f, a1 = 0.0f, a2 = 0.0f, a3 = 0.0f;
#pragma unroll
        for (int s = 0; s < WR_SLOTS; s += 4) {
            if (s + 0 < cnt) a0 += wv[s + 0] * hbuf[cur][wi[s + 0]];
            if (s + 1 < cnt) a1 += wv[s + 1] * hbuf[cur][wi[s + 1]];
            if (s + 2 < cnt) a2 += wv[s + 2] * hbuf[cur][wi[s + 2]];
            if (s + 3 < cnt) a3 += wv[s + 3] * hbuf[cur][wi[s + 3]];
        }
        float pre = ep + ((a0 + a1) + (a2 + a3));
        pre = fminf(10.0f, fmaxf(-10.0f, pre));
        float hn = (1.0f - aL) * h_my + aL * tanhf(pre);
        h_my = hn;
        ep = ep_next;
        hs_base[(size_t)t * RES] = hn;

#pragma unroll
        for (int p = 0; p < 8; p++) {
            float* dst = cl.map_shared_rank(&hbuf[nxt][row], p);
            *dst = hn;
        }
        cl.sync();
    }
}

// ---------------- 5) proj GEMM (tile 128m x 64n, 128 CTAs) fused fp16 convert ----------
__global__ __launch_bounds__(256) void proj_gemm_kernel(const float* __restrict__ B)
{
    __shared__ float As[8][128];
    __shared__ float Bs[8][64];
    const float* A = g_hs;
    const int tid = threadIdx.x;
    const int m0 = blockIdx.y * 128;
    const int n0 = blockIdx.x * 64;
    const int ty = tid >> 4;          // 0..15 -> 8 m each
    const int tx = tid & 15;          // 0..15 -> 4 n each
    const int lrow = tid >> 1;        // A loader row 0..127
    const int lk   = (tid & 1) * 4;

    unsigned long long acc[8][2];
#pragma unroll
    for (int i = 0; i < 8; i++) { acc[i][0] = 0ull; acc[i][1] = 0ull; }

    for (int k0 = 0; k0 < RES; k0 += 8) {
        float4 av = *reinterpret_cast<const float4*>(A + (size_t)(m0 + lrow) * RES + k0 + lk);
        As[lk+0][lrow] = av.x; As[lk+1][lrow] = av.y;
        As[lk+2][lrow] = av.z; As[lk+3][lrow] = av.w;
        if (tid < 128) {
            float4 bv = *reinterpret_cast<const float4*>(B + (size_t)(n0 + lrow) * RES + k0 + lk);
            Bs[lk+0][lrow] = bv.x; Bs[lk+1][lrow] = bv.y;
            Bs[lk+2][lrow] = bv.z; Bs[lk+3][lrow] = bv.w;
        }
        __syncthreads();

#pragma unroll
        for (int kk = 0; kk < 8; kk++) {
            float4 a0 = *reinterpret_cast<const float4*>(&As[kk][ty * 8]);
            float4 a1 = *reinterpret_cast<const float4*>(&As[kk][ty * 8 + 4]);
            float4 b0 = *reinterpret_cast<const float4*>(&Bs[kk][tx * 4]);
            unsigned long long b2[2] = { pk2(b0.x, b0.y), pk2(b0.z, b0.w) };
            float a[8] = { a0.x, a0.y, a0.z, a0.w, a1.x, a1.y, a1.z, a1.w };
#pragma unroll
            for (int i = 0; i < 8; i++) {
                unsigned long long a2 = pk2(a[i], a[i]);
                fma2(acc[i][0], a2, b2[0]);
                fma2(acc[i][1], a2, b2[1]);
            }
        }
        __syncthreads();
    }

    // fused epilogue: round proj to fp16 (Ah), store packed pairs
#pragma unroll
    for (int i = 0; i < 8; i++) {
        int m = m0 + ty * 8 + i;
        __half* arow = g_acat + (size_t)m * KCA;
#pragma unroll
        for (int jp = 0; jp < 2; jp++) {
            float2 v = upk2(acc[i][jp]);
            int k = n0 + tx * 4 + jp * 2;
            __half2 hp;
            hp.x = __float2half_rn(v.x);
            hp.y = __float2half_rn(v.y);
            *reinterpret_cast<__half2*>(arow + k) = hp;
        }
    }
}

// ---------------- 6) convert B to fp16 (single product: Bh only) ----------------
__global__ __launch_bounds__(256) void convert_b_kernel(const float* __restrict__ src) {
    int idx = blockIdx.x * 256 + threadIdx.x;
    if (idx >= VOCAB_PAD * (ROUT / 8)) return;
    int r  = idx >> 6;
    int k8 = (idx & 63) * 8;
    __half h[8];
    if (r < VOCAB) {
        const float* s = src + (size_t)r * ROUT + k8;
        float4 v0 = *reinterpret_cast<const float4*>(s);
        float4 v1 = *reinterpret_cast<const float4*>(s + 4);
        float vv[8] = {v0.x, v0.y, v0.z, v0.w, v1.x, v1.y, v1.z, v1.w};
#pragma unroll
        for (int i = 0; i < 8; i++) h[i] = __float2half_rn(vv[i]);
    } else {
#pragma unroll
        for (int i = 0; i < 8; i++) h[i] = __float2half_rn(0.0f);
    }
    __half* row = g_bcat + (size_t)r * KCB;
    *reinterpret_cast<uint4*>(row + k8) = *reinterpret_cast<uint4*>(h);
}

// ---------------- 7) logits GEMM via mma.sync fp16 — single product, K=512 ----------
#define KS64    8                // 512 / 64
#define STAGE2  32768            // A 16KB (128 x 128B) + B 16KB
#define SWZ2(row, c) ((row) * 128 + (((c) ^ ((row) & 7)) * 16))

__global__ __launch_bounds__(256, 2) void logits_mma_kernel(
    const float* __restrict__ bias, float* __restrict__ out)
{
    extern __shared__ __align__(128) char smem[];
    const uint32_t sbase = smem_u32(smem);
    float* bias_sm = reinterpret_cast<float*>(smem + 3 * STAGE2);

    const int tid = threadIdx.x;
    const int wid = tid >> 5;
    const int lane = tid & 31;
    const int m0 = blockIdx.x * 128;       // m fast -> wave shares B in L2
    const int n0 = blockIdx.y * 128;
    const int wm = (wid & 3) * 32;
    const int wn = (wid >> 2) * 64;

    if (tid < 128) {
        int n = n0 + tid;
        bias_sm[tid] = (n < VOCAB) ? bias[n] : 0.0f;
    }

    const char* Ab = (const char*)g_acat + (size_t)m0 * (KCA * 2);
    const char* Bb = (const char*)g_bcat + (size_t)n0 * (KCB * 2);

    auto load_stage = [&](int j, int slot) {
        const size_t kk = (size_t)j * 128;          // 64 fp16 = 128 bytes
        const uint32_t sa = sbase + slot * STAGE2;
        const uint32_t sb = sa + 16384;
#pragma unroll
        for (int i = 0; i < 4; i++) {
            int c = tid + i * 256;
            int r = c >> 3, col = c & 7;
            cp16(sa + SWZ2(r, col), Ab + (size_t)r * (KCA * 2) + kk + col * 16);
        }
#pragma unroll
        for (int i = 0; i < 4; i++) {
            int c = tid + i * 256;
            int r = c >> 3, col = c & 7;
            cp16(sb + SWZ2(r, col), Bb + (size_t)r * (KCB * 2) + kk + col * 16);
        }
    };

    int rowA[2], swA[2];
#pragma unroll
    for (int mf = 0; mf < 2; mf++) {
        rowA[mf] = wm + mf * 16 + (lane & 7) + ((lane >> 3) & 1) * 8;
        swA[mf]  = rowA[mf] & 7;
    }
    const int caddA = lane >> 4;
    int rowB[4], swB[4];
#pragma unroll
    for (int nb = 0; nb < 4; nb++) {
        rowB[nb] = wn + nb * 16 + (lane & 7) + (lane >> 4) * 8;
        swB[nb]  = rowB[nb] & 7;
    }
    const int caddB = (lane >> 3) & 1;

    float acc[2][8][4];
#pragma unroll
    for (int mf = 0; mf < 2; mf++)
#pragma unroll
        for (int nf = 0; nf < 8; nf++)
#pragma unroll
            for (int i = 0; i < 4; i++) acc[mf][nf][i] = 0.0f;

    load_stage(0, 0); cp_commit();
    load_stage(1, 1); cp_commit();

    int slot = 0;
    for (int j = 0; j < KS64; j++) {
        cp_wait<1>();
        __syncthreads();
        if (j + 2 < KS64) {
            int s2 = j + 2 - ((j + 2) / 3) * 3;     // (j+2) % 3
            load_stage(j + 2, s2);
        }
        cp_commit();

        const uint32_t sa = sbase + slot * STAGE2;
        const uint32_t sb = sa + 16384;
#pragma unroll
        for (int kk = 0; kk < 4; kk++) {
            uint32_t a[2][4], b[4][4];
#pragma unroll
            for (int mf = 0; mf < 2; mf++) {
                int c = kk * 2 + caddA;
                ldsm4(a[mf], sa + rowA[mf] * 128 + ((c ^ swA[mf]) * 16));
            }
#pragma unroll
            for (int nb = 0; nb < 4; nb++) {
                int c = kk * 2 + caddB;
                ldsm4(b[nb], sb + rowB[nb] * 128 + ((c ^ swB[nb]) * 16));
            }
#pragma unroll
            for (int mf = 0; mf < 2; mf++)
#pragma unroll
                for (int nf = 0; nf < 8; nf++)
                    mma16816(acc[mf][nf], a[mf], b[nf >> 1][(nf & 1) * 2],
                             b[nf >> 1][(nf & 1) * 2 + 1]);
        }
        if (++slot == 3) slot = 0;
    }

    // epilogue: scalar stores (VOCAB odd -> rows alternate 8B alignment)
#pragma unroll
    for (int mf = 0; mf < 2; mf++) {
        int mrow = m0 + wm + mf * 16 + (lane >> 2);
        float* crow0 = out + (size_t)mrow * VOCAB;
        float* crow1 = out + (size_t)(mrow + 8) * VOCAB;
#pragma unroll
        for (int nf = 0; nf < 8; nf++) {
            int nl = wn + nf * 8 + (lane & 3) * 2;
            int n = n0 + nl;
            if (n < VOCAB) {
                crow0[n] = acc[mf][nf][0] + bias_sm[nl];
                crow1[n] = acc[mf][nf][2] + bias_sm[nl];
            }
            if (n + 1 < VOCAB) {
                crow0[n + 1] = acc[mf][nf][1] + bias_sm[nl + 1];
                crow1[n + 1] = acc[mf][nf][3] + bias_sm[nl + 1];
            }
        }
    }
}

// ---------------- host launcher ----------------
extern "C" void kernel_launch(void* const* d_in, const int* in_sizes, int n_in,
                              void* d_out, int out_size)
{
    const int*   x    = (const int*)  d_in[0];
    const float* temb = (const float*)d_in[1];
    const float* Win  = (const float*)d_in[2];
    const float* Wrec = (const float*)d_in[3];
    const float* a    = (const float*)d_in[4];
    const float* Wb   = (const float*)d_in[5];
    const float* Wa   = (const float*)d_in[6];
    const float* bias = (const float*)d_in[7];
    const float* h0   = (const float*)d_in[8];
    float* out = (float*)d_out;

    // preprocessing (independent of recurrence)
    sparsify_wrec_kernel<<<256, 256>>>(Wrec);
    sparsify_win_kernel<<<256, 256>>>(Win);
    convert_b_kernel<<<(VOCAB_PAD * (ROUT / 8) + 255) / 256, 256>>>(Wa);

    embed_proj_kernel<<<dim3(BT / 16, 4), 256>>>(x, temb);
    recurrence_kernel<<<64, 256>>>(a, h0);

    // proj = hs @ Wb^T fused with fp16 convert -> g_acat (Ah), 128 CTAs
    proj_gemm_kernel<<<dim3(ROUT / 64, BT / 128), 256>>>(Wb);

    // logits = Ah @ Bh^T + bias (single-product fp16, K=512, 3 stages)
    const int smem_bytes = 3 * STAGE2 + 512;   // 98816
    cudaFuncSetAttribute(logits_mma_kernel,
                         cudaFuncAttributeMaxDynamicSharedMemorySize, smem_bytes);
    logits_mma_kernel<<<dim3(BT / 128, VOCAB_PAD / 128), 256, smem_bytes>>>(bias, out);
}

// round 14
// speedup vs baseline: 1.5561x; 1.0518x over previous
#include <cuda_runtime.h>
#include <cuda_bf16.h>
#include <cuda_fp16.h>
#include <cooperative_groups.h>
#include <cstdint>

namespace cg = cooperative_groups;

// ---------------- problem constants ----------------
#define VOCAB   50257
#define VOCAB_PAD 50432           // 394 * 128
#define DEMB    512
#define RES     2048
#define ROUT    512
#define BATCH   8
#define TLEN    256
#define BT      (BATCH*TLEN)      // 2048
#define KCA     512               // stored A: [Ah]  (fp16)
#define KCB     512               // stored B: [Bh]  (fp16, single product)
#define WR_SLOTS 64
#define WI_SLOTS 32
#define FULLW   0xffffffffu

// ---------------- device scratch (no allocs allowed) ----------------
__device__ float g_emb_proj[BT * RES];
__device__ float g_hs      [BT * RES];
__device__ float g_wr_val  [RES * WR_SLOTS];
__device__ int   g_wr_idx  [RES * WR_SLOTS];
__device__ int   g_wr_cnt  [RES];
__device__ float g_wi_val  [RES * WI_SLOTS];
__device__ int   g_wi_idx  [RES * WI_SLOTS];
__device__ __half g_acat[BT * KCA];            // 2.1 MB
__device__ __half g_bcat[VOCAB_PAD * KCB];     // 51.6 MB

// ---------------- small PTX helpers (sm_80-compatible only) ----------------
__device__ __forceinline__ uint32_t smem_u32(const void* p) {
    uint32_t a;
    asm("{ .reg .u64 t; cvta.to.shared.u64 t, %1; cvt.u32.u64 %0, t; }" : "=r"(a) : "l"(p));
    return a;
}
__device__ __forceinline__ void cp16(uint32_t saddr, const void* g) {
    asm volatile("cp.async.cg.shared.global [%0], [%1], 16;" :: "r"(saddr), "l"(g) : "memory");
}
__device__ __forceinline__ void cp_commit() { asm volatile("cp.async.commit_group;" ::: "memory"); }
template<int N> __device__ __forceinline__ void cp_wait() {
    asm volatile("cp.async.wait_group %0;" :: "n"(N) : "memory");
}
__device__ __forceinline__ void ldsm4(uint32_t r[4], uint32_t addr) {
    asm volatile("ldmatrix.sync.aligned.m8n8.x4.shared.b16 {%0,%1,%2,%3}, [%4];"
                 : "=r"(r[0]), "=r"(r[1]), "=r"(r[2]), "=r"(r[3]) : "r"(addr));
}
__device__ __forceinline__ void mma16816(float c[4], const uint32_t a[4],
                                         uint32_t b0, uint32_t b1) {
    asm volatile("mma.sync.aligned.m16n8k16.row.col.f32.f16.f16.f32 "
                 "{%0,%1,%2,%3}, {%4,%5,%6,%7}, {%8,%9}, {%0,%1,%2,%3};"
                 : "+f"(c[0]), "+f"(c[1]), "+f"(c[2]), "+f"(c[3])
                 : "r"(a[0]), "r"(a[1]), "r"(a[2]), "r"(a[3]), "r"(b0), "r"(b1));
}

// ---------------- f32x2 packed-FMA helpers (proj GEMM) ----------------
__device__ __forceinline__ unsigned long long pk2(float x, float y) {
    unsigned long long r;
    asm("mov.b64 %0, {%1, %2};" : "=l"(r) : "f"(x), "f"(y));
    return r;
}
__device__ __forceinline__ void fma2(unsigned long long& d, unsigned long long a, unsigned long long b) {
    asm("fma.rn.f32x2 %0, %1, %2, %0;" : "+l"(d) : "l"(a), "l"(b));
}
__device__ __forceinline__ float2 upk2(unsigned long long v) {
    float2 r;
    asm("mov.b64 {%0, %1}, %2;" : "=f"(r.x), "=f"(r.y) : "l"(v));
    return r;
}

// ---------------- 1) sparsify W_rec ----------------
__global__ void sparsify_wrec_kernel(const float* __restrict__ W) {
    int warp = blockIdx.x * (blockDim.x >> 5) + (threadIdx.x >> 5);
    int lane = threadIdx.x & 31;
    if (warp >= RES) return;
    const float* row = W + (size_t)warp * RES;
    int base = 0;
    for (int j0 = 0; j0 < RES; j0 += 32) {
        float v = row[j0 + lane];
        unsigned m = __ballot_sync(FULLW, v != 0.0f);
        int pref = __popc(m & ((1u << lane) - 1u));
        if (v != 0.0f) {
            int pos = base + pref;
            if (pos < WR_SLOTS) {
                g_wr_val[warp * WR_SLOTS + pos] = v;
                g_wr_idx[warp * WR_SLOTS + pos] = j0 + lane;
            }
        }
        base += __popc(m);
    }
    int bb = base < WR_SLOTS ? base : WR_SLOTS;
    if (lane == 0) g_wr_cnt[warp] = bb;
    for (int s = bb + lane; s < WR_SLOTS; s += 32) {
        g_wr_val[warp * WR_SLOTS + s] = 0.0f;
        g_wr_idx[warp * WR_SLOTS + s] = 0;
    }
}

// ---------------- 2) sparsify W_in ----------------
__global__ void sparsify_win_kernel(const float* __restrict__ W) {
    int col  = blockIdx.x * (blockDim.x >> 5) + (threadIdx.x >> 5);
    int lane = threadIdx.x & 31;
    if (col >= RES) return;
    int base = 0;
    for (int d0 = 0; d0 < DEMB; d0 += 32) {
        float v = W[(size_t)(d0 + lane) * RES + col];
        unsigned m = __ballot_sync(FULLW, v != 0.0f);
        int pref = __popc(m & ((1u << lane) - 1u));
        if (v != 0.0f) {
            int pos = base + pref;
            if (pos < WI_SLOTS) {
                g_wi_val[col * WI_SLOTS + pos] = v;
                g_wi_idx[col * WI_SLOTS + pos] = d0 + lane;
            }
        }
        base += __popc(m);
    }
    int bb = base < WI_SLOTS ? base : WI_SLOTS;
    for (int s = bb + lane; s < WI_SLOTS; s += 32) {
        g_wi_val[col * WI_SLOTS + s] = 0.0f;
        g_wi_idx[col * WI_SLOTS + s] = 0;
    }
}

// ---------------- 3) embed + sparse input projection (vectorized wv/wi) ----------------
__global__ __launch_bounds__(256) void embed_proj_kernel(
    const int* __restrict__ xg, const float* __restrict__ tok_emb)
{
    __shared__ __align__(16) float emb_sm[DEMB][20];
    const int bt0 = blockIdx.x * 16;
    const int rbase = blockIdx.y * 512;
    const int tid = threadIdx.x;

    for (int idx = tid; idx < 16 * DEMB; idx += 256) {
        int i = idx >> 9;
        int d = idx & (DEMB - 1);
        int tok = xg[bt0 + i];
        emb_sm[d][i] = tok_emb[(size_t)tok * DEMB + d];
    }
    __syncthreads();

    for (int r = rbase + tid; r < rbase + 512; r += 256) {
        float acc[16];
#pragma unroll
        for (int i = 0; i < 16; i++) acc[i] = 0.0f;
        const float* vrow = g_wi_val + (size_t)r * WI_SLOTS;
        const int*   irow = g_wi_idx + (size_t)r * WI_SLOTS;
#pragma unroll
        for (int s = 0; s < WI_SLOTS; s += 4) {
            float4 v4 = *reinterpret_cast<const float4*>(vrow + s);
            int4   d4 = *reinterpret_cast<const int4*>(irow + s);
            float vs[4] = {v4.x, v4.y, v4.z, v4.w};
            int   ds[4] = {d4.x, d4.y, d4.z, d4.w};
#pragma unroll
            for (int u = 0; u < 4; u++) {
                if (vs[u] != 0.0f) {
#pragma unroll
                    for (int i0 = 0; i0 < 16; i0 += 4) {
                        float4 e = *reinterpret_cast<const float4*>(&emb_sm[ds[u]][i0]);
                        acc[i0+0] += vs[u] * e.x; acc[i0+1] += vs[u] * e.y;
                        acc[i0+2] += vs[u] * e.z; acc[i0+3] += vs[u] * e.w;
                    }
                }
            }
        }
#pragma unroll
        for (int i = 0; i < 16; i++)
            g_emb_proj[(size_t)(bt0 + i) * RES + r] = acc[i];
    }
}

// ---------------- 4) recurrence (R10 form, frozen) ----------------
__global__ void __cluster_dims__(8, 1, 1) __launch_bounds__(256, 1)
recurrence_kernel(const float* __restrict__ a_leak, const float* __restrict__ h0)
{
    __shared__ float hbuf[2][RES];
    cg::cluster_group cl = cg::this_cluster();

    const int tid  = threadIdx.x;
    const int b    = blockIdx.x >> 3;
    const int rank = (int)cl.block_rank();
    const int row  = rank * 256 + tid;

    float wv[WR_SLOTS];
    int   wi[WR_SLOTS];
    const int cnt = g_wr_cnt[row];
#pragma unroll
    for (int s = 0; s < WR_SLOTS; s++) {
        wv[s] = g_wr_val[row * WR_SLOTS + s];
        wi[s] = g_wr_idx[row * WR_SLOTS + s];
    }

    for (int j = tid; j < RES; j += 256) hbuf[0][j] = h0[j];
    const float aL   = a_leak[row];
    float       h_my = h0[row];
    __syncthreads();

    const float* ep_base = g_emb_proj + (size_t)b * TLEN * RES + row;
    float*       hs_base = g_hs       + (size_t)b * TLEN * RES + row;

    float ep = ep_base[0];
    for (int t = 0; t < TLEN; t++) {
        const int cur = t & 1, nxt = cur ^ 1;
        float ep_next = (t + 1 < TLEN) ? ep_base[(size_t)(t + 1) * RES] : 0.0f;
        float a0 = 0.0f, a1 = 0.0f, a2 = 0.0f, a3 = 0.0f;
#pragma unroll
        for (int s = 0; s < WR_SLOTS; s += 4) {
            if (s + 0 < cnt) a0 += wv[s + 0] * hbuf[cur][wi[s + 0]];
            if (s + 1 < cnt) a1 += wv[s + 1] * hbuf[cur][wi[s + 1]];
            if (s + 2 < cnt) a2 += wv[s + 2] * hbuf[cur][wi[s + 2]];
            if (s + 3 < cnt) a3 += wv[s + 3] * hbuf[cur][wi[s + 3]];
        }
        float pre = ep + ((a0 + a1) + (a2 + a3));
        pre = fminf(10.0f, fmaxf(-10.0f, pre));
        float hn = (1.0f - aL) * h_my + aL * tanhf(pre);
        h_my = hn;
        ep = ep_next;
        hs_base[(size_t)t * RES] = hn;

#pragma unroll
        for (int p = 0; p < 8; p++) {
            float* dst = cl.map_shared_rank(&hbuf[nxt][row], p);
            *dst = hn;
        }
        cl.sync();
    }
}

// ---------------- 5) proj GEMM (128m x 64n) + register-prefetch pipeline ----------------
__global__ __launch_bounds__(256) void proj_gemm_kernel(const float* __restrict__ B)
{
    __shared__ float As[8][128];
    __shared__ float Bs[8][64];
    const float* A = g_hs;
    const int tid = threadIdx.x;
    const int m0 = blockIdx.y * 128;
    const int n0 = blockIdx.x * 64;
    const int ty = tid >> 4;          // 0..15 -> 8 m each
    const int tx = tid & 15;          // 0..15 -> 4 n each
    const int lrow = tid >> 1;        // A loader row 0..127
    const int lk   = (tid & 1) * 4;

    unsigned long long acc[8][2];
#pragma unroll
    for (int i = 0; i < 8; i++) { acc[i][0] = 0ull; acc[i][1] = 0ull; }

    const float* aptr = A + (size_t)(m0 + lrow) * RES + lk;
    const float* bptr = B + (size_t)(n0 + lrow) * RES + lk;

    // prologue: fetch k0 = 0 tile into registers
    float4 av = *reinterpret_cast<const float4*>(aptr);
    float4 bv = make_float4(0.f, 0.f, 0.f, 0.f);
    if (tid < 128) bv = *reinterpret_cast<const float4*>(bptr);

    for (int k0 = 0; k0 < RES; k0 += 8) {
        // store current tile to smem
        As[lk+0][lrow] = av.x; As[lk+1][lrow] = av.y;
        As[lk+2][lrow] = av.z; As[lk+3][lrow] = av.w;
        if (tid < 128) {
            Bs[lk+0][lrow] = bv.x; Bs[lk+1][lrow] = bv.y;
            Bs[lk+2][lrow] = bv.z; Bs[lk+3][lrow] = bv.w;
        }
        __syncthreads();

        // prefetch next tile into registers (latency hidden under compute)
        if (k0 + 8 < RES) {
            av = *reinterpret_cast<const float4*>(aptr + k0 + 8);
            if (tid < 128) bv = *reinterpret_cast<const float4*>(bptr + k0 + 8);
        }

#pragma unroll
        for (int kk = 0; kk < 8; kk++) {
            float4 a0 = *reinterpret_cast<const float4*>(&As[kk][ty * 8]);
            float4 a1 = *reinterpret_cast<const float4*>(&As[kk][ty * 8 + 4]);
            float4 b0 = *reinterpret_cast<const float4*>(&Bs[kk][tx * 4]);
            unsigned long long b2[2] = { pk2(b0.x, b0.y), pk2(b0.z, b0.w) };
            float a[8] = { a0.x, a0.y, a0.z, a0.w, a1.x, a1.y, a1.z, a1.w };
#pragma unroll
            for (int i = 0; i < 8; i++) {
                unsigned long long a2 = pk2(a[i], a[i]);
                fma2(acc[i][0], a2, b2[0]);
                fma2(acc[i][1], a2, b2[1]);
            }
        }
        __syncthreads();
    }

    // fused epilogue: round proj to fp16 (Ah), store packed pairs
#pragma unroll
    for (int i = 0; i < 8; i++) {
        int m = m0 + ty * 8 + i;
        __half* arow = g_acat + (size_t)m * KCA;
#pragma unroll
        for (int jp = 0; jp < 2; jp++) {
            float2 v = upk2(acc[i][jp]);
            int k = n0 + tx * 4 + jp * 2;
            __half2 hp;
            hp.x = __float2half_rn(v.x);
            hp.y = __float2half_rn(v.y);
            *reinterpret_cast<__half2*>(arow + k) = hp;
        }
    }
}

// ---------------- 6) convert B to fp16 (single product: Bh only) ----------------
__global__ __launch_bounds__(256) void convert_b_kernel(const float* __restrict__ src) {
    int idx = blockIdx.x * 256 + threadIdx.x;
    if (idx >= VOCAB_PAD * (ROUT / 8)) return;
    int r  = idx >> 6;
    int k8 = (idx & 63) * 8;
    __half h[8];
    if (r < VOCAB) {
        const float* s = src + (size_t)r * ROUT + k8;
        float4 v0 = *reinterpret_cast<const float4*>(s);
        float4 v1 = *reinterpret_cast<const float4*>(s + 4);
        float vv[8] = {v0.x, v0.y, v0.z, v0.w, v1.x, v1.y, v1.z, v1.w};
#pragma unroll
        for (int i = 0; i < 8; i++) h[i] = __float2half_rn(vv[i]);
    } else {
#pragma unroll
        for (int i = 0; i < 8; i++) h[i] = __float2half_rn(0.0f);
    }
    __half* row = g_bcat + (size_t)r * KCB;
    *reinterpret_cast<uint4*>(row + k8) = *reinterpret_cast<uint4*>(h);
}

// ---------------- 7) logits GEMM via mma.sync fp16 — single product, K=512 ----------
#define KS64    8                // 512 / 64
#define STAGE2  32768            // A 16KB (128 x 128B) + B 16KB
#define SWZ2(row, c) ((row) * 128 + (((c) ^ ((row) & 7)) * 16))

__global__ __launch_bounds__(256, 2) void logits_mma_kernel(
    const float* __restrict__ bias, float* __restrict__ out)
{
    extern __shared__ __align__(128) char smem[];
    const uint32_t sbase = smem_u32(smem);
    float* bias_sm = reinterpret_cast<float*>(smem + 3 * STAGE2);

    const int tid = threadIdx.x;
    const int wid = tid >> 5;
    const int lane = tid & 31;
    const int m0 = blockIdx.x * 128;       // m fast -> wave shares B in L2
    const int n0 = blockIdx.y * 128;
    const int wm = (wid & 3) * 32;
    const int wn = (wid >> 2) * 64;

    if (tid < 128) {
        int n = n0 + tid;
        bias_sm[tid] = (n < VOCAB) ? bias[n] : 0.0f;
    }

    const char* Ab = (const char*)g_acat + (size_t)m0 * (KCA * 2);
    const char* Bb = (const char*)g_bcat + (size_t)n0 * (KCB * 2);

    auto load_stage = [&](int j, int slot) {
        const size_t kk = (size_t)j * 128;          // 64 fp16 = 128 bytes
        const uint32_t sa = sbase + slot * STAGE2;
        const uint32_t sb = sa + 16384;
#pragma unroll
        for (int i = 0; i < 4; i++) {
            int c = tid + i * 256;
            int r = c >> 3, col = c & 7;
            cp16(sa + SWZ2(r, col), Ab + (size_t)r * (KCA * 2) + kk + col * 16);
        }
#pragma unroll
        for (int i = 0; i < 4; i++) {
            int c = tid + i * 256;
            int r = c >> 3, col = c & 7;
            cp16(sb + SWZ2(r, col), Bb + (size_t)r * (KCB * 2) + kk + col * 16);
        }
    };

    int rowA[2], swA[2];
#pragma unroll
    for (int mf = 0; mf < 2; mf++) {
        rowA[mf] = wm + mf * 16 + (lane & 7) + ((lane >> 3) & 1) * 8;
        swA[mf]  = rowA[mf] & 7;
    }
    const int caddA = lane >> 4;
    int rowB[4], swB[4];
#pragma unroll
    for (int nb = 0; nb < 4; nb++) {
        rowB[nb] = wn + nb * 16 + (lane & 7) + (lane >> 4) * 8;
        swB[nb]  = rowB[nb] & 7;
    }
    const int caddB = (lane >> 3) & 1;

    float acc[2][8][4];
#pragma unroll
    for (int mf = 0; mf < 2; mf++)
#pragma unroll
        for (int nf = 0; nf < 8; nf++)
#pragma unroll
            for (int i = 0; i < 4; i++) acc[mf][nf][i] = 0.0f;

    load_stage(0, 0); cp_commit();
    load_stage(1, 1); cp_commit();

    int slot = 0;
    for (int j = 0; j < KS64; j++) {
        cp_wait<1>();
        __syncthreads();
        if (j + 2 < KS64) {
            int s2 = j + 2 - ((j + 2) / 3) * 3;     // (j+2) % 3
            load_stage(j + 2, s2);
        }
        cp_commit();

        const uint32_t sa = sbase + slot * STAGE2;
        const uint32_t sb = sa + 16384;
#pragma unroll
        for (int kk = 0; kk < 4; kk++) {
            uint32_t a[2][4], b[4][4];
#pragma unroll
            for (int mf = 0; mf < 2; mf++) {
                int c = kk * 2 + caddA;
                ldsm4(a[mf], sa + rowA[mf] * 128 + ((c ^ swA[mf]) * 16));
            }
#pragma unroll
            for (int nb = 0; nb < 4; nb++) {
                int c = kk * 2 + caddB;
                ldsm4(b[nb], sb + rowB[nb] * 128 + ((c ^ swB[nb]) * 16));
            }
#pragma unroll
            for (int mf = 0; mf < 2; mf++)
#pragma unroll
                for (int nf = 0; nf < 8; nf++)
                    mma16816(acc[mf][nf], a[mf], b[nf >> 1][(nf & 1) * 2],
                             b[nf >> 1][(nf & 1) * 2 + 1]);
        }
        if (++slot == 3) slot = 0;
    }

    // epilogue: scalar stores (VOCAB odd -> rows alternate 8B alignment)
#pragma unroll
    for (int mf = 0; mf < 2; mf++) {
        int mrow = m0 + wm + mf * 16 + (lane >> 2);
        float* crow0 = out + (size_t)mrow * VOCAB;
        float* crow1 = out + (size_t)(mrow + 8) * VOCAB;
#pragma unroll
        for (int nf = 0; nf < 8; nf++) {
            int nl = wn + nf * 8 + (lane & 3) * 2;
            int n = n0 + nl;
            if (n < VOCAB) {
                crow0[n] = acc[mf][nf][0] + bias_sm[nl];
                crow1[n] = acc[mf][nf][2] + bias_sm[nl];
            }
            if (n + 1 < VOCAB) {
                crow0[n + 1] = acc[mf][nf][1] + bias_sm[nl + 1];
                crow1[n + 1] = acc[mf][nf][3] + bias_sm[nl + 1];
            }
        }
    }
}

// ---------------- host launcher ----------------
extern "C" void kernel_launch(void* const* d_in, const int* in_sizes, int n_in,
                              void* d_out, int out_size)
{
    const int*   x    = (const int*)  d_in[0];
    const float* temb = (const float*)d_in[1];
    const float* Win  = (const float*)d_in[2];
    const float* Wrec = (const float*)d_in[3];
    const float* a    = (const float*)d_in[4];
    const float* Wb   = (const float*)d_in[5];
    const float* Wa   = (const float*)d_in[6];
    const float* bias = (const float*)d_in[7];
    const float* h0   = (const float*)d_in[8];
    float* out = (float*)d_out;

    // preprocessing (independent of recurrence)
    sparsify_wrec_kernel<<<256, 256>>>(Wrec);
    sparsify_win_kernel<<<256, 256>>>(Win);
    convert_b_kernel<<<(VOCAB_PAD * (ROUT / 8) + 255) / 256, 256>>>(Wa);

    embed_proj_kernel<<<dim3(BT / 16, 4), 256>>>(x, temb);
    recurrence_kernel<<<64, 256>>>(a, h0);

    // proj = hs @ Wb^T fused with fp16 convert -> g_acat (Ah), 128 CTAs
    proj_gemm_kernel<<<dim3(ROUT / 64, BT / 128), 256>>>(Wb);

    // logits = Ah @ Bh^T + bias (single-product fp16, K=512, 3 stages)
    const int smem_bytes = 3 * STAGE2 + 512;   // 98816
    cudaFuncSetAttribute(logits_mma_kernel,
                         cudaFuncAttributeMaxDynamicSharedMemorySize, smem_bytes);
    logits_mma_kernel<<<dim3(BT / 128, VOCAB_PAD / 128), 256, smem_bytes>>>(bias, out);
}

// round 15
// speedup vs baseline: 1.5738x; 1.0114x over previous
#include <cuda_runtime.h>
#include <cuda_bf16.h>
#include <cuda_fp16.h>
#include <cooperative_groups.h>
#include <cstdint>

namespace cg = cooperative_groups;

// ---------------- problem constants ----------------
#define VOCAB   50257
#define VOCAB_PAD 50432           // 394 * 128
#define DEMB    512
#define RES     2048
#define ROUT    512
#define BATCH   8
#define TLEN    256
#define BT      (BATCH*TLEN)      // 2048
#define KCA     512               // stored A: [Ah]  (fp16)
#define KCB     512               // stored B: [Bh]  (fp16, single product)
#define WR_SLOTS 64
#define WI_SLOTS 32
#define FULLW   0xffffffffu

// ---------------- device scratch (no allocs allowed) ----------------
__device__ float g_emb_proj[BT * RES];
__device__ float g_hs      [BT * RES];
__device__ float g_wr_val  [RES * WR_SLOTS];
__device__ int   g_wr_idx  [RES * WR_SLOTS];
__device__ int   g_wr_cnt  [RES];
__device__ float g_wi_val  [RES * WI_SLOTS];
__device__ int   g_wi_idx  [RES * WI_SLOTS];
__device__ __half g_acat[BT * KCA];            // 2.1 MB
__device__ __half g_bcat[VOCAB_PAD * KCB];     // 51.6 MB

// ---------------- small PTX helpers (sm_80-compatible only) ----------------
__device__ __forceinline__ uint32_t smem_u32(const void* p) {
    uint32_t a;
    asm("{ .reg .u64 t; cvta.to.shared.u64 t, %1; cvt.u32.u64 %0, t; }" : "=r"(a) : "l"(p));
    return a;
}
__device__ __forceinline__ void cp16(uint32_t saddr, const void* g) {
    asm volatile("cp.async.cg.shared.global [%0], [%1], 16;" :: "r"(saddr), "l"(g) : "memory");
}
__device__ __forceinline__ void cp_commit() { asm volatile("cp.async.commit_group;" ::: "memory"); }
template<int N> __device__ __forceinline__ void cp_wait() {
    asm volatile("cp.async.wait_group %0;" :: "n"(N) : "memory");
}
__device__ __forceinline__ void ldsm4(uint32_t r[4], uint32_t addr) {
    asm volatile("ldmatrix.sync.aligned.m8n8.x4.shared.b16 {%0,%1,%2,%3}, [%4];"
                 : "=r"(r[0]), "=r"(r[1]), "=r"(r[2]), "=r"(r[3]) : "r"(addr));
}
__device__ __forceinline__ void mma16816(float c[4], const uint32_t a[4],
                                         uint32_t b0, uint32_t b1) {
    asm volatile("mma.sync.aligned.m16n8k16.row.col.f32.f16.f16.f32 "
                 "{%0,%1,%2,%3}, {%4,%5,%6,%7}, {%8,%9}, {%0,%1,%2,%3};"
                 : "+f"(c[0]), "+f"(c[1]), "+f"(c[2]), "+f"(c[3])
                 : "r"(a[0]), "r"(a[1]), "r"(a[2]), "r"(a[3]), "r"(b0), "r"(b1));
}

// ---------------- f32x2 packed-FMA helpers (proj GEMM) ----------------
__device__ __forceinline__ unsigned long long pk2(float x, float y) {
    unsigned long long r;
    asm("mov.b64 %0, {%1, %2};" : "=l"(r) : "f"(x), "f"(y));
    return r;
}
__device__ __forceinline__ void fma2(unsigned long long& d, unsigned long long a, unsigned long long b) {
    asm("fma.rn.f32x2 %0, %1, %2, %0;" : "+l"(d) : "l"(a), "l"(b));
}
__device__ __forceinline__ float2 upk2(unsigned long long v) {
    float2 r;
    asm("mov.b64 {%0, %1}, %2;" : "=f"(r.x), "=f"(r.y) : "l"(v));
    return r;
}

// ---------------- 1) fused preprocessing: convert_b | sparsify_wrec | sparsify_win ------
// blockIdx ranges: [0, NB_CVT) convert_b, [NB_CVT, NB_CVT+256) wrec, [.., +256) win
#define NB_CVT ((VOCAB_PAD * (ROUT / 8) + 255) / 256)     // 12608

__device__ void do_convert_b(int blk, int tid, const float* __restrict__ src) {
    int idx = blk * 256 + tid;
    if (idx >= VOCAB_PAD * (ROUT / 8)) return;
    int r  = idx >> 6;
    int k8 = (idx & 63) * 8;
    __half h[8];
    if (r < VOCAB) {
        const float* s = src + (size_t)r * ROUT + k8;
        float4 v0 = *reinterpret_cast<const float4*>(s);
        float4 v1 = *reinterpret_cast<const float4*>(s + 4);
        float vv[8] = {v0.x, v0.y, v0.z, v0.w, v1.x, v1.y, v1.z, v1.w};
#pragma unroll
        for (int i = 0; i < 8; i++) h[i] = __float2half_rn(vv[i]);
    } else {
#pragma unroll
        for (int i = 0; i < 8; i++) h[i] = __float2half_rn(0.0f);
    }
    __half* row = g_bcat + (size_t)r * KCB;
    *reinterpret_cast<uint4*>(row + k8) = *reinterpret_cast<uint4*>(h);
}

__device__ void do_sparsify_wrec(int blk, int tid, const float* __restrict__ W) {
    int warp = blk * 8 + (tid >> 5);
    int lane = tid & 31;
    if (warp >= RES) return;
    const float* row = W + (size_t)warp * RES;
    int base = 0;
    for (int j0 = 0; j0 < RES; j0 += 32) {
        float v = row[j0 + lane];
        unsigned m = __ballot_sync(FULLW, v != 0.0f);
        int pref = __popc(m & ((1u << lane) - 1u));
        if (v != 0.0f) {
            int pos = base + pref;
            if (pos < WR_SLOTS) {
                g_wr_val[warp * WR_SLOTS + pos] = v;
                g_wr_idx[warp * WR_SLOTS + pos] = j0 + lane;
            }
        }
        base += __popc(m);
    }
    int bb = base < WR_SLOTS ? base : WR_SLOTS;
    if (lane == 0) g_wr_cnt[warp] = bb;
    for (int s = bb + lane; s < WR_SLOTS; s += 32) {
        g_wr_val[warp * WR_SLOTS + s] = 0.0f;
        g_wr_idx[warp * WR_SLOTS + s] = 0;
    }
}

__device__ void do_sparsify_win(int blk, int tid, const float* __restrict__ W) {
    int col  = blk * 8 + (tid >> 5);
    int lane = tid & 31;
    if (col >= RES) return;
    int base = 0;
    for (int d0 = 0; d0 < DEMB; d0 += 32) {
        float v = W[(size_t)(d0 + lane) * RES + col];
        unsigned m = __ballot_sync(FULLW, v != 0.0f);
        int pref = __popc(m & ((1u << lane) - 1u));
        if (v != 0.0f) {
            int pos = base + pref;
            if (pos < WI_SLOTS) {
                g_wi_val[col * WI_SLOTS + pos] = v;
                g_wi_idx[col * WI_SLOTS + pos] = d0 + lane;
            }
        }
        base += __popc(m);
    }
    int bb = base < WI_SLOTS ? base : WI_SLOTS;
    for (int s = bb + lane; s < WI_SLOTS; s += 32) {
        g_wi_val[col * WI_SLOTS + s] = 0.0f;
        g_wi_idx[col * WI_SLOTS + s] = 0;
    }
}

__global__ __launch_bounds__(256) void preprocess_kernel(
    const float* __restrict__ Wa, const float* __restrict__ Wrec,
    const float* __restrict__ Win)
{
    const int blk = blockIdx.x;
    const int tid = threadIdx.x;
    if (blk < NB_CVT)                do_convert_b(blk, tid, Wa);
    else if (blk < NB_CVT + 256)     do_sparsify_wrec(blk - NB_CVT, tid, Wrec);
    else                             do_sparsify_win(blk - NB_CVT - 256, tid, Win);
}

// ---------------- 3) embed + sparse input projection (vectorized wv/wi) ----------------
__global__ __launch_bounds__(256) void embed_proj_kernel(
    const int* __restrict__ xg, const float* __restrict__ tok_emb)
{
    __shared__ __align__(16) float emb_sm[DEMB][20];
    const int bt0 = blockIdx.x * 16;
    const int rbase = blockIdx.y * 512;
    const int tid = threadIdx.x;

    for (int idx = tid; idx < 16 * DEMB; idx += 256) {
        int i = idx >> 9;
        int d = idx & (DEMB - 1);
        int tok = xg[bt0 + i];
        emb_sm[d][i] = tok_emb[(size_t)tok * DEMB + d];
    }
    __syncthreads();

    for (int r = rbase + tid; r < rbase + 512; r += 256) {
        float acc[16];
#pragma unroll
        for (int i = 0; i < 16; i++) acc[i] = 0.0f;
        const float* vrow = g_wi_val + (size_t)r * WI_SLOTS;
        const int*   irow = g_wi_idx + (size_t)r * WI_SLOTS;
#pragma unroll
        for (int s = 0; s < WI_SLOTS; s += 4) {
            float4 v4 = *reinterpret_cast<const float4*>(vrow + s);
            int4   d4 = *reinterpret_cast<const int4*>(irow + s);
            float vs[4] = {v4.x, v4.y, v4.z, v4.w};
            int   ds[4] = {d4.x, d4.y, d4.z, d4.w};
#pragma unroll
            for (int u = 0; u < 4; u++) {
                if (vs[u] != 0.0f) {
#pragma unroll
                    for (int i0 = 0; i0 < 16; i0 += 4) {
                        float4 e = *reinterpret_cast<const float4*>(&emb_sm[ds[u]][i0]);
                        acc[i0+0] += vs[u] * e.x; acc[i0+1] += vs[u] * e.y;
                        acc[i0+2] += vs[u] * e.z; acc[i0+3] += vs[u] * e.w;
                    }
                }
            }
        }
#pragma unroll
        for (int i = 0; i < 16; i++)
            g_emb_proj[(size_t)(bt0 + i) * RES + r] = acc[i];
    }
}

// ---------------- 4) recurrence (R10 form, frozen) ----------------
__global__ void __cluster_dims__(8, 1, 1) __launch_bounds__(256, 1)
recurrence_kernel(const float* __restrict__ a_leak, const float* __restrict__ h0)
{
    __shared__ float hbuf[2][RES];
    cg::cluster_group cl = cg::this_cluster();

    const int tid  = threadIdx.x;
    const int b    = blockIdx.x >> 3;
    const int rank = (int)cl.block_rank();
    const int row  = rank * 256 + tid;

    float wv[WR_SLOTS];
    int   wi[WR_SLOTS];
    const int cnt = g_wr_cnt[row];
#pragma unroll
    for (int s = 0; s < WR_SLOTS; s++) {
        wv[s] = g_wr_val[row * WR_SLOTS + s];
        wi[s] = g_wr_idx[row * WR_SLOTS + s];
    }

    for (int j = tid; j < RES; j += 256) hbuf[0][j] = h0[j];
    const float aL   = a_leak[row];
    float       h_my = h0[row];
    __syncthreads();

    const float* ep_base = g_emb_proj + (size_t)b * TLEN * RES + row;
    float*       hs_base = g_hs       + (size_t)b * TLEN * RES + row;

    float ep = ep_base[0];
    for (int t = 0; t < TLEN; t++) {
        const int cur = t & 1, nxt = cur ^ 1;
        float ep_next = (t + 1 < TLEN) ? ep_base[(size_t)(t + 1) * RES] : 0.0f;
        float a0 = 0.0f, a1 = 0.0f, a2 = 0.0f, a3 = 0.0f;
#pragma unroll
        for (int s = 0; s < WR_SLOTS; s += 4) {
            if (s + 0 < cnt) a0 += wv[s + 0] * hbuf[cur][wi[s + 0]];
            if (s + 1 < cnt) a1 += wv[s + 1] * hbuf[cur][wi[s + 1]];
            if (s + 2 < cnt) a2 += wv[s + 2] * hbuf[cur][wi[s + 2]];
            if (s + 3 < cnt) a3 += wv[s + 3] * hbuf[cur][wi[s + 3]];
        }
        float pre = ep + ((a0 + a1) + (a2 + a3));
        pre = fminf(10.0f, fmaxf(-10.0f, pre));
        float hn = (1.0f - aL) * h_my + aL * tanhf(pre);
        h_my = hn;
        ep = ep_next;
        hs_base[(size_t)t * RES] = hn;

#pragma unroll
        for (int p = 0; p < 8; p++) {
            float* dst = cl.map_shared_rank(&hbuf[nxt][row], p);
            *dst = hn;
        }
        cl.sync();
    }
}

// ---------------- 5) proj GEMM (128m x 64n) + register-prefetch pipeline ----------------
__global__ __launch_bounds__(256) void proj_gemm_kernel(const float* __restrict__ B)
{
    __shared__ float As[8][128];
    __shared__ float Bs[8][64];
    const float* A = g_hs;
    const int tid = threadIdx.x;
    const int m0 = blockIdx.y * 128;
    const int n0 = blockIdx.x * 64;
    const int ty = tid >> 4;
    const int tx = tid & 15;
    const int lrow = tid >> 1;
    const int lk   = (tid & 1) * 4;

    unsigned long long acc[8][2];
#pragma unroll
    for (int i = 0; i < 8; i++) { acc[i][0] = 0ull; acc[i][1] = 0ull; }

    const float* aptr = A + (size_t)(m0 + lrow) * RES + lk;
    const float* bptr = B + (size_t)(n0 + lrow) * RES + lk;

    float4 av = *reinterpret_cast<const float4*>(aptr);
    float4 bv = make_float4(0.f, 0.f, 0.f, 0.f);
    if (tid < 128) bv = *reinterpret_cast<const float4*>(bptr);

    for (int k0 = 0; k0 < RES; k0 += 8) {
        As[lk+0][lrow] = av.x; As[lk+1][lrow] = av.y;
        As[lk+2][lrow] = av.z; As[lk+3][lrow] = av.w;
        if (tid < 128) {
            Bs[lk+0][lrow] = bv.x; Bs[lk+1][lrow] = bv.y;
            Bs[lk+2][lrow] = bv.z; Bs[lk+3][lrow] = bv.w;
        }
        __syncthreads();

        if (k0 + 8 < RES) {
            av = *reinterpret_cast<const float4*>(aptr + k0 + 8);
            if (tid < 128) bv = *reinterpret_cast<const float4*>(bptr + k0 + 8);
        }

#pragma unroll
        for (int kk = 0; kk < 8; kk++) {
            float4 a0 = *reinterpret_cast<const float4*>(&As[kk][ty * 8]);
            float4 a1 = *reinterpret_cast<const float4*>(&As[kk][ty * 8 + 4]);
            float4 b0 = *reinterpret_cast<const float4*>(&Bs[kk][tx * 4]);
            unsigned long long b2[2] = { pk2(b0.x, b0.y), pk2(b0.z, b0.w) };
            float a[8] = { a0.x, a0.y, a0.z, a0.w, a1.x, a1.y, a1.z, a1.w };
#pragma unroll
            for (int i = 0; i < 8; i++) {
                unsigned long long a2 = pk2(a[i], a[i]);
                fma2(acc[i][0], a2, b2[0]);
                fma2(acc[i][1], a2, b2[1]);
            }
        }
        __syncthreads();
    }

#pragma unroll
    for (int i = 0; i < 8; i++) {
        int m = m0 + ty * 8 + i;
        __half* arow = g_acat + (size_t)m * KCA;
#pragma unroll
        for (int jp = 0; jp < 2; jp++) {
            float2 v = upk2(acc[i][jp]);
            int k = n0 + tx * 4 + jp * 2;
            __half2 hp;
            hp.x = __float2half_rn(v.x);
            hp.y = __float2half_rn(v.y);
            *reinterpret_cast<__half2*>(arow + k) = hp;
        }
    }
}

// ---------------- 7) logits GEMM — single product fp16, kk fragment double-buffer ------
#define KS64    8                // 512 / 64
#define STAGE2  32768            // A 16KB (128 x 128B) + B 16KB
#define SWZ2(row, c) ((row) * 128 + (((c) ^ ((row) & 7)) * 16))

__global__ __launch_bounds__(256, 2) void logits_mma_kernel(
    const float* __restrict__ bias, float* __restrict__ out)
{
    extern __shared__ __align__(128) char smem[];
    const uint32_t sbase = smem_u32(smem);
    float* bias_sm = reinterpret_cast<float*>(smem + 3 * STAGE2);

    const int tid = threadIdx.x;
    const int wid = tid >> 5;
    const int lane = tid & 31;
    const int m0 = blockIdx.x * 128;       // m fast -> wave shares B in L2
    const int n0 = blockIdx.y * 128;
    const int wm = (wid & 3) * 32;
    const int wn = (wid >> 2) * 64;

    if (tid < 128) {
        int n = n0 + tid;
        bias_sm[tid] = (n < VOCAB) ? bias[n] : 0.0f;
    }

    const char* Ab = (const char*)g_acat + (size_t)m0 * (KCA * 2);
    const char* Bb = (const char*)g_bcat + (size_t)n0 * (KCB * 2);

    auto load_stage = [&](int j, int slot) {
        const size_t kk = (size_t)j * 128;          // 64 fp16 = 128 bytes
        const uint32_t sa = sbase + slot * STAGE2;
        const uint32_t sb = sa + 16384;
#pragma unroll
        for (int i = 0; i < 4; i++) {
            int c = tid + i * 256;
            int r = c >> 3, col = c & 7;
            cp16(sa + SWZ2(r, col), Ab + (size_t)r * (KCA * 2) + kk + col * 16);
        }
#pragma unroll
        for (int i = 0; i < 4; i++) {
            int c = tid + i * 256;
            int r = c >> 3, col = c & 7;
            cp16(sb + SWZ2(r, col), Bb + (size_t)r * (KCB * 2) + kk + col * 16);
        }
    };

    int rowA[2], swA[2];
#pragma unroll
    for (int mf = 0; mf < 2; mf++) {
        rowA[mf] = wm + mf * 16 + (lane & 7) + ((lane >> 3) & 1) * 8;
        swA[mf]  = rowA[mf] & 7;
    }
    const int caddA = lane >> 4;
    int rowB[4], swB[4];
#pragma unroll
    for (int nb = 0; nb < 4; nb++) {
        rowB[nb] = wn + nb * 16 + (lane & 7) + (lane >> 4) * 8;
        swB[nb]  = rowB[nb] & 7;
    }
    const int caddB = (lane >> 3) & 1;

    float acc[2][8][4];
#pragma unroll
    for (int mf = 0; mf < 2; mf++)
#pragma unroll
        for (int nf = 0; nf < 8; nf++)
#pragma unroll
            for (int i = 0; i < 4; i++) acc[mf][nf][i] = 0.0f;

    load_stage(0, 0); cp_commit();
    load_stage(1, 1); cp_commit();

    int slot = 0;
    for (int j = 0; j < KS64; j++) {
        cp_wait<1>();
        __syncthreads();
        if (j + 2 < KS64) {
            int s2 = j + 2 - ((j + 2) / 3) * 3;     // (j+2) % 3
            load_stage(j + 2, s2);
        }
        cp_commit();

        const uint32_t sa = sbase + slot * STAGE2;
        const uint32_t sb = sa + 16384;

        // fragment double-buffer across kk: LDSM for kk+1 issued before MMA of kk
        uint32_t a[2][2][4], b[2][4][4];
        int cur = 0;
#pragma unroll
        for (int mf = 0; mf < 2; mf++)
            ldsm4(a[cur][mf], sa + rowA[mf] * 128 + ((caddA ^ swA[mf]) * 16));
#pragma unroll
        for (int nb = 0; nb < 4; nb++)
            ldsm4(b[cur][nb], sb + rowB[nb] * 128 + ((caddB ^ swB[nb]) * 16));

#pragma unroll
        for (int kk = 0; kk < 4; kk++) {
            const int nxt = cur ^ 1;
            if (kk < 3) {
                const int cA = (kk + 1) * 2 + caddA;
                const int cB = (kk + 1) * 2 + caddB;
#pragma unroll
                for (int mf = 0; mf < 2; mf++)
                    ldsm4(a[nxt][mf], sa + rowA[mf] * 128 + ((cA ^ swA[mf]) * 16));
#pragma unroll
                for (int nb = 0; nb < 4; nb++)
                    ldsm4(b[nxt][nb], sb + rowB[nb] * 128 + ((cB ^ swB[nb]) * 16));
            }
#pragma unroll
            for (int mf = 0; mf < 2; mf++)
#pragma unroll
                for (int nf = 0; nf < 8; nf++)
                    mma16816(acc[mf][nf], a[cur][mf], b[cur][nf >> 1][(nf & 1) * 2],
                             b[cur][nf >> 1][(nf & 1) * 2 + 1]);
            cur = nxt;
        }
        if (++slot == 3) slot = 0;
    }

    // epilogue: scalar stores (VOCAB odd -> rows alternate 8B alignment)
#pragma unroll
    for (int mf = 0; mf < 2; mf++) {
        int mrow = m0 + wm + mf * 16 + (lane >> 2);
        float* crow0 = out + (size_t)mrow * VOCAB;
        float* crow1 = out + (size_t)(mrow + 8) * VOCAB;
#pragma unroll
        for (int nf = 0; nf < 8; nf++) {
            int nl = wn + nf * 8 + (lane & 3) * 2;
            int n = n0 + nl;
            if (n < VOCAB) {
                crow0[n] = acc[mf][nf][0] + bias_sm[nl];
                crow1[n] = acc[mf][nf][2] + bias_sm[nl];
            }
            if (n + 1 < VOCAB) {
                crow0[n + 1] = acc[mf][nf][1] + bias_sm[nl + 1];
                crow1[n + 1] = acc[mf][nf][3] + bias_sm[nl + 1];
            }
        }
    }
}

// ---------------- host launcher ----------------
extern "C" void kernel_launch(void* const* d_in, const int* in_sizes, int n_in,
                              void* d_out, int out_size)
{
    const int*   x    = (const int*)  d_in[0];
    const float* temb = (const float*)d_in[1];
    const float* Win  = (const float*)d_in[2];
    const float* Wrec = (const float*)d_in[3];
    const float* a    = (const float*)d_in[4];
    const float* Wb   = (const float*)d_in[5];
    const float* Wa   = (const float*)d_in[6];
    const float* bias = (const float*)d_in[7];
    const float* h0   = (const float*)d_in[8];
    float* out = (float*)d_out;

    // fused preprocessing: convert_b + sparsify_wrec + sparsify_win in one launch
    preprocess_kernel<<<NB_CVT + 512, 256>>>(Wa, Wrec, Win);

    embed_proj_kernel<<<dim3(BT / 16, 4), 256>>>(x, temb);
    recurrence_kernel<<<64, 256>>>(a, h0);

    // proj = hs @ Wb^T fused with fp16 convert -> g_acat (Ah), 128 CTAs
    proj_gemm_kernel<<<dim3(ROUT / 64, BT / 128), 256>>>(Wb);

    // logits = Ah @ Bh^T + bias (single-product fp16, K=512, 3 stages)
    const int smem_bytes = 3 * STAGE2 + 512;   // 98816
    cudaFuncSetAttribute(logits_mma_kernel,
                         cudaFuncAttributeMaxDynamicSharedMemorySize, smem_bytes);
    logits_mma_kernel<<<dim3(BT / 128, VOCAB_PAD / 128), 256, smem_bytes>>>(bias, out);
}

// round 16
// speedup vs baseline: 1.8881x; 1.1997x over previous
#include <cuda_runtime.h>
#include <cuda_bf16.h>
#include <cuda_fp16.h>
#include <cooperative_groups.h>
#include <cstdint>

namespace cg = cooperative_groups;

// ---------------- problem constants ----------------
#define VOCAB   50257
#define VOCAB_PAD 50432           // 394 * 128
#define DEMB    512
#define RES     2048
#define ROUT    512
#define BATCH   8
#define TLEN    256
#define BT      (BATCH*TLEN)      // 2048
#define KCA     512               // stored A: [Ah]  (fp16)
#define KCB     512               // stored B: [Bh]  (fp16, single product)
#define WR_SLOTS 64
#define WI_SLOTS 32
#define FULLW   0xffffffffu

// ---------------- device scratch (no allocs allowed) ----------------
__device__ float  g_emb_proj[BT * RES];
__device__ __half g_hs_h    [BT * RES];        // 8.4 MB (fp16 readout copy of hs)
__device__ __half g_wb_h    [ROUT * RES];      // 2.1 MB (fp16 Wb)
__device__ float  g_wr_val  [RES * WR_SLOTS];
__device__ int    g_wr_idx  [RES * WR_SLOTS];
__device__ int    g_wr_cnt  [RES];
__device__ float  g_wi_val  [RES * WI_SLOTS];
__device__ int    g_wi_idx  [RES * WI_SLOTS];
__device__ __half g_acat[BT * KCA];            // 2.1 MB
__device__ __half g_bcat[VOCAB_PAD * KCB];     // 51.6 MB

// ---------------- small PTX helpers (sm_80-compatible only) ----------------
__device__ __forceinline__ uint32_t smem_u32(const void* p) {
    uint32_t a;
    asm("{ .reg .u64 t; cvta.to.shared.u64 t, %1; cvt.u32.u64 %0, t; }" : "=r"(a) : "l"(p));
    return a;
}
__device__ __forceinline__ void cp16(uint32_t saddr, const void* g) {
    asm volatile("cp.async.cg.shared.global [%0], [%1], 16;" :: "r"(saddr), "l"(g) : "memory");
}
__device__ __forceinline__ void cp_commit() { asm volatile("cp.async.commit_group;" ::: "memory"); }
template<int N> __device__ __forceinline__ void cp_wait() {
    asm volatile("cp.async.wait_group %0;" :: "n"(N) : "memory");
}
__device__ __forceinline__ void ldsm4(uint32_t r[4], uint32_t addr) {
    asm volatile("ldmatrix.sync.aligned.m8n8.x4.shared.b16 {%0,%1,%2,%3}, [%4];"
                 : "=r"(r[0]), "=r"(r[1]), "=r"(r[2]), "=r"(r[3]) : "r"(addr));
}
__device__ __forceinline__ void mma16816(float c[4], const uint32_t a[4],
                                         uint32_t b0, uint32_t b1) {
    asm volatile("mma.sync.aligned.m16n8k16.row.col.f32.f16.f16.f32 "
                 "{%0,%1,%2,%3}, {%4,%5,%6,%7}, {%8,%9}, {%0,%1,%2,%3};"
                 : "+f"(c[0]), "+f"(c[1]), "+f"(c[2]), "+f"(c[3])
                 : "r"(a[0]), "r"(a[1]), "r"(a[2]), "r"(a[3]), "r"(b0), "r"(b1));
}

// ---------------- 1) fused preprocessing ----------------
// blocks: [0, NB_CVT) convert Wa->Bh | [+256) sparsify Wrec | [+256) sparsify Win
//         | [+NB_WB) convert Wb->fp16
#define NB_CVT ((VOCAB_PAD * (ROUT / 8) + 255) / 256)     // 12608
#define NB_WB  ((ROUT * RES / 8) / 256)                   // 512

__device__ void do_convert_b(int blk, int tid, const float* __restrict__ src) {
    int idx = blk * 256 + tid;
    if (idx >= VOCAB_PAD * (ROUT / 8)) return;
    int r  = idx >> 6;
    int k8 = (idx & 63) * 8;
    __half h[8];
    if (r < VOCAB) {
        const float* s = src + (size_t)r * ROUT + k8;
        float4 v0 = *reinterpret_cast<const float4*>(s);
        float4 v1 = *reinterpret_cast<const float4*>(s + 4);
        float vv[8] = {v0.x, v0.y, v0.z, v0.w, v1.x, v1.y, v1.z, v1.w};
#pragma unroll
        for (int i = 0; i < 8; i++) h[i] = __float2half_rn(vv[i]);
    } else {
#pragma unroll
        for (int i = 0; i < 8; i++) h[i] = __float2half_rn(0.0f);
    }
    __half* row = g_bcat + (size_t)r * KCB;
    *reinterpret_cast<uint4*>(row + k8) = *reinterpret_cast<uint4*>(h);
}

__device__ void do_convert_wb(int blk, int tid, const float* __restrict__ src) {
    int idx = (blk * 256 + tid) * 8;           // over ROUT*RES
    if (idx >= ROUT * RES) return;
    float4 v0 = *reinterpret_cast<const float4*>(src + idx);
    float4 v1 = *reinterpret_cast<const float4*>(src + idx + 4);
    float vv[8] = {v0.x, v0.y, v0.z, v0.w, v1.x, v1.y, v1.z, v1.w};
    __half h[8];
#pragma unroll
    for (int i = 0; i < 8; i++) h[i] = __float2half_rn(vv[i]);
    *reinterpret_cast<uint4*>(g_wb_h + idx) = *reinterpret_cast<uint4*>(h);
}

__device__ void do_sparsify_wrec(int blk, int tid, const float* __restrict__ W) {
    int warp = blk * 8 + (tid >> 5);
    int lane = tid & 31;
    if (warp >= RES) return;
    const float* row = W + (size_t)warp * RES;
    int base = 0;
    for (int j0 = 0; j0 < RES; j0 += 32) {
        float v = row[j0 + lane];
        unsigned m = __ballot_sync(FULLW, v != 0.0f);
        int pref = __popc(m & ((1u << lane) - 1u));
        if (v != 0.0f) {
            int pos = base + pref;
            if (pos < WR_SLOTS) {
                g_wr_val[warp * WR_SLOTS + pos] = v;
                g_wr_idx[warp * WR_SLOTS + pos] = j0 + lane;
            }
        }
        base += __popc(m);
    }
    int bb = base < WR_SLOTS ? base : WR_SLOTS;
    if (lane == 0) g_wr_cnt[warp] = bb;
    for (int s = bb + lane; s < WR_SLOTS; s += 32) {
        g_wr_val[warp * WR_SLOTS + s] = 0.0f;
        g_wr_idx[warp * WR_SLOTS + s] = 0;
    }
}

__device__ void do_sparsify_win(int blk, int tid, const float* __restrict__ W) {
    int col  = blk * 8 + (tid >> 5);
    int lane = tid & 31;
    if (col >= RES) return;
    int base = 0;
    for (int d0 = 0; d0 < DEMB; d0 += 32) {
        float v = W[(size_t)(d0 + lane) * RES + col];
        unsigned m = __ballot_sync(FULLW, v != 0.0f);
        int pref = __popc(m & ((1u << lane) - 1u));
        if (v != 0.0f) {
            int pos = base + pref;
            if (pos < WI_SLOTS) {
                g_wi_val[col * WI_SLOTS + pos] = v;
                g_wi_idx[col * WI_SLOTS + pos] = d0 + lane;
            }
        }
        base += __popc(m);
    }
    int bb = base < WI_SLOTS ? base : WI_SLOTS;
    for (int s = bb + lane; s < WI_SLOTS; s += 32) {
        g_wi_val[col * WI_SLOTS + s] = 0.0f;
        g_wi_idx[col * WI_SLOTS + s] = 0;
    }
}

__global__ __launch_bounds__(256) void preprocess_kernel(
    const float* __restrict__ Wa, const float* __restrict__ Wrec,
    const float* __restrict__ Win, const float* __restrict__ Wb)
{
    const int blk = blockIdx.x;
    const int tid = threadIdx.x;
    if (blk < NB_CVT)                    do_convert_b(blk, tid, Wa);
    else if (blk < NB_CVT + 256)         do_sparsify_wrec(blk - NB_CVT, tid, Wrec);
    else if (blk < NB_CVT + 512)         do_sparsify_win(blk - NB_CVT - 256, tid, Win);
    else                                 do_convert_wb(blk - NB_CVT - 512, tid, Wb);
}

// ---------------- 3) embed + sparse input projection (vectorized wv/wi) ----------------
__global__ __launch_bounds__(256) void embed_proj_kernel(
    const int* __restrict__ xg, const float* __restrict__ tok_emb)
{
    __shared__ __align__(16) float emb_sm[DEMB][20];
    const int bt0 = blockIdx.x * 16;
    const int rbase = blockIdx.y * 512;
    const int tid = threadIdx.x;

    for (int idx = tid; idx < 16 * DEMB; idx += 256) {
        int i = idx >> 9;
        int d = idx & (DEMB - 1);
        int tok = xg[bt0 + i];
        emb_sm[d][i] = tok_emb[(size_t)tok * DEMB + d];
    }
    __syncthreads();

    for (int r = rbase + tid; r < rbase + 512; r += 256) {
        float acc[16];
#pragma unroll
        for (int i = 0; i < 16; i++) acc[i] = 0.0f;
        const float* vrow = g_wi_val + (size_t)r * WI_SLOTS;
        const int*   irow = g_wi_idx + (size_t)r * WI_SLOTS;
#pragma unroll
        for (int s = 0; s < WI_SLOTS; s += 4) {
            float4 v4 = *reinterpret_cast<const float4*>(vrow + s);
            int4   d4 = *reinterpret_cast<const int4*>(irow + s);
            float vs[4] = {v4.x, v4.y, v4.z, v4.w};
            int   ds[4] = {d4.x, d4.y, d4.z, d4.w};
#pragma unroll
            for (int u = 0; u < 4; u++) {
                if (vs[u] != 0.0f) {
#pragma unroll
                    for (int i0 = 0; i0 < 16; i0 += 4) {
                        float4 e = *reinterpret_cast<const float4*>(&emb_sm[ds[u]][i0]);
                        acc[i0+0] += vs[u] * e.x; acc[i0+1] += vs[u] * e.y;
                        acc[i0+2] += vs[u] * e.z; acc[i0+3] += vs[u] * e.w;
                    }
                }
            }
        }
#pragma unroll
        for (int i = 0; i < 16; i++)
            g_emb_proj[(size_t)(bt0 + i) * RES + r] = acc[i];
    }
}

// ---------------- 4) recurrence (R10 form; hs stored as fp16) ----------------
__global__ void __cluster_dims__(8, 1, 1) __launch_bounds__(256, 1)
recurrence_kernel(const float* __restrict__ a_leak, const float* __restrict__ h0)
{
    __shared__ float hbuf[2][RES];
    cg::cluster_group cl = cg::this_cluster();

    const int tid  = threadIdx.x;
    const int b    = blockIdx.x >> 3;
    const int rank = (int)cl.block_rank();
    const int row  = rank * 256 + tid;

    float wv[WR_SLOTS];
    int   wi[WR_SLOTS];
    const int cnt = g_wr_cnt[row];
#pragma unroll
    for (int s = 0; s < WR_SLOTS; s++) {
        wv[s] = g_wr_val[row * WR_SLOTS + s];
        wi[s] = g_wr_idx[row * WR_SLOTS + s];
    }

    for (int j = tid; j < RES; j += 256) hbuf[0][j] = h0[j];
    const float aL   = a_leak[row];
    float       h_my = h0[row];
    __syncthreads();

    const float* ep_base = g_emb_proj + (size_t)b * TLEN * RES + row;
    __half*      hs_base = g_hs_h     + (size_t)b * TLEN * RES + row;

    float ep = ep_base[0];
    for (int t = 0; t < TLEN; t++) {
        const int cur = t & 1, nxt = cur ^ 1;
        float ep_next = (t + 1 < TLEN) ? ep_base[(size_t)(t + 1) * RES] : 0.0f;
        float a0 = 0.0f, a1 = 0.0f, a2 = 0.0f, a3 = 0.0f;
#pragma unroll
        for (int s = 0; s < WR_SLOTS; s += 4) {
            if (s + 0 < cnt) a0 += wv[s + 0] * hbuf[cur][wi[s + 0]];
            if (s + 1 < cnt) a1 += wv[s + 1] * hbuf[cur][wi[s + 1]];
            if (s + 2 < cnt) a2 += wv[s + 2] * hbuf[cur][wi[s + 2]];
            if (s + 3 < cnt) a3 += wv[s + 3] * hbuf[cur][wi[s + 3]];
        }
        float pre = ep + ((a0 + a1) + (a2 + a3));
        pre = fminf(10.0f, fmaxf(-10.0f, pre));
        float hn = (1.0f - aL) * h_my + aL * tanhf(pre);
        h_my = hn;
        ep = ep_next;
        hs_base[(size_t)t * RES] = __float2half_rn(hn);   // fp16 readout copy

#pragma unroll
        for (int p = 0; p < 8; p++) {
            float* dst = cl.map_shared_rank(&hbuf[nxt][row], p);
            *dst = hn;
        }
        cl.sync();
    }
}

// ---------------- shared fp16 MMA tile machinery ----------------
#define STAGE2  32768            // A 16KB (128 x 128B) + B 16KB
#define SWZ2(row, c) ((row) * 128 + (((c) ^ ((row) & 7)) * 16))

// ---------------- 5) proj GEMM via mma.sync fp16: g_acat = fp16(hs_h @ Wb_h^T) --------
#define KSP     32               // 2048 / 64

__global__ __launch_bounds__(256, 2) void proj_mma_kernel()
{
    extern __shared__ __align__(128) char smem[];
    const uint32_t sbase = smem_u32(smem);

    const int tid = threadIdx.x;
    const int wid = tid >> 5;
    const int lane = tid & 31;
    const int m0 = blockIdx.x * 128;
    const int n0 = blockIdx.y * 128;
    const int wm = (wid & 3) * 32;
    const int wn = (wid >> 2) * 64;

    const char* Ab = (const char*)g_hs_h + (size_t)m0 * (RES * 2);
    const char* Bb = (const char*)g_wb_h + (size_t)n0 * (RES * 2);

    auto load_stage = [&](int j, int slot) {
        const size_t kk = (size_t)j * 128;          // 64 fp16 = 128 bytes
        const uint32_t sa = sbase + slot * STAGE2;
        const uint32_t sb = sa + 16384;
#pragma unroll
        for (int i = 0; i < 4; i++) {
            int c = tid + i * 256;
            int r = c >> 3, col = c & 7;
            cp16(sa + SWZ2(r, col), Ab + (size_t)r * (RES * 2) + kk + col * 16);
        }
#pragma unroll
        for (int i = 0; i < 4; i++) {
            int c = tid + i * 256;
            int r = c >> 3, col = c & 7;
            cp16(sb + SWZ2(r, col), Bb + (size_t)r * (RES * 2) + kk + col * 16);
        }
    };

    int rowA[2], swA[2];
#pragma unroll
    for (int mf = 0; mf < 2; mf++) {
        rowA[mf] = wm + mf * 16 + (lane & 7) + ((lane >> 3) & 1) * 8;
        swA[mf]  = rowA[mf] & 7;
    }
    const int caddA = lane >> 4;
    int rowB[4], swB[4];
#pragma unroll
    for (int nb = 0; nb < 4; nb++) {
        rowB[nb] = wn + nb * 16 + (lane & 7) + (lane >> 4) * 8;
        swB[nb]  = rowB[nb] & 7;
    }
    const int caddB = (lane >> 3) & 1;

    float acc[2][8][4];
#pragma unroll
    for (int mf = 0; mf < 2; mf++)
#pragma unroll
        for (int nf = 0; nf < 8; nf++)
#pragma unroll
            for (int i = 0; i < 4; i++) acc[mf][nf][i] = 0.0f;

    load_stage(0, 0); cp_commit();
    load_stage(1, 1); cp_commit();

    int slot = 0;
    for (int j = 0; j < KSP; j++) {
        cp_wait<1>();
        __syncthreads();
        if (j + 2 < KSP) {
            int s2 = j + 2 - ((j + 2) / 3) * 3;
            load_stage(j + 2, s2);
        }
        cp_commit();

        const uint32_t sa = sbase + slot * STAGE2;
        const uint32_t sb = sa + 16384;

        uint32_t a[2][2][4], b[2][4][4];
        int cur = 0;
#pragma unroll
        for (int mf = 0; mf < 2; mf++)
            ldsm4(a[cur][mf], sa + rowA[mf] * 128 + ((caddA ^ swA[mf]) * 16));
#pragma unroll
        for (int nb = 0; nb < 4; nb++)
            ldsm4(b[cur][nb], sb + rowB[nb] * 128 + ((caddB ^ swB[nb]) * 16));

#pragma unroll
        for (int kk = 0; kk < 4; kk++) {
            const int nxt = cur ^ 1;
            if (kk < 3) {
                const int cA = (kk + 1) * 2 + caddA;
                const int cB = (kk + 1) * 2 + caddB;
#pragma unroll
                for (int mf = 0; mf < 2; mf++)
                    ldsm4(a[nxt][mf], sa + rowA[mf] * 128 + ((cA ^ swA[mf]) * 16));
#pragma unroll
                for (int nb = 0; nb < 4; nb++)
                    ldsm4(b[nxt][nb], sb + rowB[nb] * 128 + ((cB ^ swB[nb]) * 16));
            }
#pragma unroll
            for (int mf = 0; mf < 2; mf++)
#pragma unroll
                for (int nf = 0; nf < 8; nf++)
                    mma16816(acc[mf][nf], a[cur][mf], b[cur][nf >> 1][(nf & 1) * 2],
                             b[cur][nf >> 1][(nf & 1) * 2 + 1]);
            cur = nxt;
        }
        if (++slot == 3) slot = 0;
    }

    // epilogue: round to fp16, paired stores into g_acat (KCA=512 stride)
#pragma unroll
    for (int mf = 0; mf < 2; mf++) {
        int mrow = m0 + wm + mf * 16 + (lane >> 2);
        __half* arow0 = g_acat + (size_t)mrow * KCA;
        __half* arow1 = g_acat + (size_t)(mrow + 8) * KCA;
#pragma unroll
        for (int nf = 0; nf < 8; nf++) {
            int n = n0 + wn + nf * 8 + (lane & 3) * 2;
            __half2 p0, p1;
            p0.x = __float2half_rn(acc[mf][nf][0]);
            p0.y = __float2half_rn(acc[mf][nf][1]);
            p1.x = __float2half_rn(acc[mf][nf][2]);
            p1.y = __float2half_rn(acc[mf][nf][3]);
            *reinterpret_cast<__half2*>(arow0 + n) = p0;
            *reinterpret_cast<__half2*>(arow1 + n) = p1;
        }
    }
}

// ---------------- 7) logits GEMM — single product fp16, kk fragment double-buffer ------
#define KS64    8                // 512 / 64

__global__ __launch_bounds__(256, 2) void logits_mma_kernel(
    const float* __restrict__ bias, float* __restrict__ out)
{
    extern __shared__ __align__(128) char smem[];
    const uint32_t sbase = smem_u32(smem);
    float* bias_sm = reinterpret_cast<float*>(smem + 3 * STAGE2);

    const int tid = threadIdx.x;
    const int wid = tid >> 5;
    const int lane = tid & 31;
    const int m0 = blockIdx.x * 128;       // m fast -> wave shares B in L2
    const int n0 = blockIdx.y * 128;
    const int wm = (wid & 3) * 32;
    const int wn = (wid >> 2) * 64;

    if (tid < 128) {
        int n = n0 + tid;
        bias_sm[tid] = (n < VOCAB) ? bias[n] : 0.0f;
    }

    const char* Ab = (const char*)g_acat + (size_t)m0 * (KCA * 2);
    const char* Bb = (const char*)g_bcat + (size_t)n0 * (KCB * 2);

    auto load_stage = [&](int j, int slot) {
        const size_t kk = (size_t)j * 128;
        const uint32_t sa = sbase + slot * STAGE2;
        const uint32_t sb = sa + 16384;
#pragma unroll
        for (int i = 0; i < 4; i++) {
            int c = tid + i * 256;
            int r = c >> 3, col = c & 7;
            cp16(sa + SWZ2(r, col), Ab + (size_t)r * (KCA * 2) + kk + col * 16);
        }
#pragma unroll
        for (int i = 0; i < 4; i++) {
            int c = tid + i * 256;
            int r = c >> 3, col = c & 7;
            cp16(sb + SWZ2(r, col), Bb + (size_t)r * (KCB * 2) + kk + col * 16);
        }
    };

    int rowA[2], swA[2];
#pragma unroll
    for (int mf = 0; mf < 2; mf++) {
        rowA[mf] = wm + mf * 16 + (lane & 7) + ((lane >> 3) & 1) * 8;
        swA[mf]  = rowA[mf] & 7;
    }
    const int caddA = lane >> 4;
    int rowB[4], swB[4];
#pragma unroll
    for (int nb = 0; nb < 4; nb++) {
        rowB[nb] = wn + nb * 16 + (lane & 7) + (lane >> 4) * 8;
        swB[nb]  = rowB[nb] & 7;
    }
    const int caddB = (lane >> 3) & 1;

    float acc[2][8][4];
#pragma unroll
    for (int mf = 0; mf < 2; mf++)
#pragma unroll
        for (int nf = 0; nf < 8; nf++)
#pragma unroll
            for (int i = 0; i < 4; i++) acc[mf][nf][i] = 0.0f;

    load_stage(0, 0); cp_commit();
    load_stage(1, 1); cp_commit();

    int slot = 0;
    for (int j = 0; j < KS64; j++) {
        cp_wait<1>();
        __syncthreads();
        if (j + 2 < KS64) {
            int s2 = j + 2 - ((j + 2) / 3) * 3;
            load_stage(j + 2, s2);
        }
        cp_commit();

        const uint32_t sa = sbase + slot * STAGE2;
        const uint32_t sb = sa + 16384;

        uint32_t a[2][2][4], b[2][4][4];
        int cur = 0;
#pragma unroll
        for (int mf = 0; mf < 2; mf++)
            ldsm4(a[cur][mf], sa + rowA[mf] * 128 + ((caddA ^ swA[mf]) * 16));
#pragma unroll
        for (int nb = 0; nb < 4; nb++)
            ldsm4(b[cur][nb], sb + rowB[nb] * 128 + ((caddB ^ swB[nb]) * 16));

#pragma unroll
        for (int kk = 0; kk < 4; kk++) {
            const int nxt = cur ^ 1;
            if (kk < 3) {
                const int cA = (kk + 1) * 2 + caddA;
                const int cB = (kk + 1) * 2 + caddB;
#pragma unroll
                for (int mf = 0; mf < 2; mf++)
                    ldsm4(a[nxt][mf], sa + rowA[mf] * 128 + ((cA ^ swA[mf]) * 16));
#pragma unroll
                for (int nb = 0; nb < 4; nb++)
                    ldsm4(b[nxt][nb], sb + rowB[nb] * 128 + ((cB ^ swB[nb]) * 16));
            }
#pragma unroll
            for (int mf = 0; mf < 2; mf++)
#pragma unroll
                for (int nf = 0; nf < 8; nf++)
                    mma16816(acc[mf][nf], a[cur][mf], b[cur][nf >> 1][(nf & 1) * 2],
                             b[cur][nf >> 1][(nf & 1) * 2 + 1]);
            cur = nxt;
        }
        if (++slot == 3) slot = 0;
    }

    // epilogue: scalar stores (VOCAB odd -> rows alternate 8B alignment)
#pragma unroll
    for (int mf = 0; mf < 2; mf++) {
        int mrow = m0 + wm + mf * 16 + (lane >> 2);
        float* crow0 = out + (size_t)mrow * VOCAB;
        float* crow1 = out + (size_t)(mrow + 8) * VOCAB;
#pragma unroll
        for (int nf = 0; nf < 8; nf++) {
            int nl = wn + nf * 8 + (lane & 3) * 2;
            int n = n0 + nl;
            if (n < VOCAB) {
                crow0[n] = acc[mf][nf][0] + bias_sm[nl];
                crow1[n] = acc[mf][nf][2] + bias_sm[nl];
            }
            if (n + 1 < VOCAB) {
                crow0[n + 1] = acc[mf][nf][1] + bias_sm[nl + 1];
                crow1[n + 1] = acc[mf][nf][3] + bias_sm[nl + 1];
            }
        }
    }
}

// ---------------- host launcher ----------------
extern "C" void kernel_launch(void* const* d_in, const int* in_sizes, int n_in,
                              void* d_out, int out_size)
{
    const int*   x    = (const int*)  d_in[0];
    const float* temb = (const float*)d_in[1];
    const float* Win  = (const float*)d_in[2];
    const float* Wrec = (const float*)d_in[3];
    const float* a    = (const float*)d_in[4];
    const float* Wb   = (const float*)d_in[5];
    const float* Wa   = (const float*)d_in[6];
    const float* bias = (const float*)d_in[7];
    const float* h0   = (const float*)d_in[8];
    float* out = (float*)d_out;

    // fused preprocessing: Wa->Bh, sparsify Wrec/Win, Wb->fp16
    preprocess_kernel<<<NB_CVT + 512 + NB_WB, 256>>>(Wa, Wrec, Win, Wb);

    embed_proj_kernel<<<dim3(BT / 16, 4), 256>>>(x, temb);
    recurrence_kernel<<<64, 256>>>(a, h0);

    // proj (fp16 MMA): g_acat = fp16(hs_h @ Wb_h^T)
    const int smem_proj = 3 * STAGE2;          // 98304
    cudaFuncSetAttribute(proj_mma_kernel,
                         cudaFuncAttributeMaxDynamicSharedMemorySize, smem_proj);
    proj_mma_kernel<<<dim3(BT / 128, ROUT / 128), 256, smem_proj>>>();

    // logits = Ah @ Bh^T + bias (single-product fp16, K=512, 3 stages)
    const int smem_bytes = 3 * STAGE2 + 512;   // 98816
    cudaFuncSetAttribute(logits_mma_kernel,
                         cudaFuncAttributeMaxDynamicSharedMemorySize, smem_bytes);
    logits_mma_kernel<<<dim3(BT / 128, VOCAB_PAD / 128), 256, smem_bytes>>>(bias, out);
}